// round 2
// baseline (speedup 1.0000x reference)
#include <cuda_runtime.h>
#include <cstdint>
#include <math.h>

#define BATCH 4
#define SEQ   2048
#define DMODEL 1024
#define NHEADS 16
#define DK    64
#define MTOT  (BATCH*SEQ)      // 8192
#define NEGV  (-1e9f)

// Scratch (alloc-free rule: __device__ globals). 4 x 32 MB.
__device__ float g_Q[MTOT * DMODEL];
__device__ float g_K[MTOT * DMODEL];
__device__ float g_V[MTOT * DMODEL];
__device__ float g_C[MTOT * DMODEL];

// ---------------------------------------------------------------------------
// GEMM: Y[M, D] = A[M, D] @ W[D, D] + bias   (all fp32, row-major)
// 128x128 tile, K-tile 16, 256 threads, 8x8 per thread.
// ---------------------------------------------------------------------------
#define GBM 128
#define GBN 128
#define GBK 16

__global__ __launch_bounds__(256) void gemm_bias(
    const float* __restrict__ A, const float* __restrict__ W,
    const float* __restrict__ bias, float* __restrict__ Y)
{
    __shared__ float As[GBK][GBM];   // A^T tile
    __shared__ float Bs[GBK][GBN];   // W tile

    const int bm = blockIdx.y * GBM;
    const int bn = blockIdx.x * GBN;
    const int tid = threadIdx.x;
    const int tx = tid & 15;         // 0..15 -> col groups
    const int ty = tid >> 4;         // 0..15 -> row groups

    float acc[8][8];
#pragma unroll
    for (int i = 0; i < 8; i++)
#pragma unroll
        for (int j = 0; j < 8; j++) acc[i][j] = 0.f;

    for (int k0 = 0; k0 < DMODEL; k0 += GBK) {
        // Load A tile (128 rows x 16 cols) transposed into As: 512 float4, 2/thread
#pragma unroll
        for (int i = 0; i < 2; i++) {
            int f  = tid * 2 + i;            // 0..511
            int r  = f >> 2;                 // row in tile
            int cg = (f & 3) * 4;            // col 0,4,8,12
            float4 v = *(const float4*)(A + (size_t)(bm + r) * DMODEL + k0 + cg);
            As[cg + 0][r] = v.x; As[cg + 1][r] = v.y;
            As[cg + 2][r] = v.z; As[cg + 3][r] = v.w;
        }
        // Load W tile (16 rows x 128 cols): 512 float4, 2/thread
#pragma unroll
        for (int i = 0; i < 2; i++) {
            int f  = tid * 2 + i;
            int r  = f >> 5;                 // 0..15
            int cg = (f & 31) * 4;           // 0..124
            *(float4*)(&Bs[r][cg]) =
                *(const float4*)(W + (size_t)(k0 + r) * DMODEL + bn + cg);
        }
        __syncthreads();

#pragma unroll
        for (int k = 0; k < GBK; k++) {
            float a[8], b[8];
#pragma unroll
            for (int i = 0; i < 4; i++) {
                a[i]     = As[k][ty * 4 + i];
                a[4 + i] = As[k][64 + ty * 4 + i];
            }
#pragma unroll
            for (int j = 0; j < 4; j++) {
                b[j]     = Bs[k][tx * 4 + j];
                b[4 + j] = Bs[k][64 + tx * 4 + j];
            }
#pragma unroll
            for (int i = 0; i < 8; i++)
#pragma unroll
                for (int j = 0; j < 8; j++)
                    acc[i][j] += a[i] * b[j];
        }
        __syncthreads();
    }

    // Epilogue: + bias, coalesced float4 stores
    float bb[8];
#pragma unroll
    for (int j = 0; j < 4; j++) {
        bb[j]     = __ldg(bias + bn + tx * 4 + j);
        bb[4 + j] = __ldg(bias + bn + 64 + tx * 4 + j);
    }
#pragma unroll
    for (int ii = 0; ii < 8; ii++) {
        int r = bm + ((ii < 4) ? (ty * 4 + ii) : (64 + ty * 4 + ii - 4));
#pragma unroll
        for (int jj = 0; jj < 2; jj++) {
            int c = bn + jj * 64 + tx * 4;
            float4 v;
            v.x = acc[ii][jj * 4 + 0] + bb[jj * 4 + 0];
            v.y = acc[ii][jj * 4 + 1] + bb[jj * 4 + 1];
            v.z = acc[ii][jj * 4 + 2] + bb[jj * 4 + 2];
            v.w = acc[ii][jj * 4 + 3] + bb[jj * 4 + 3];
            *(float4*)(Y + (size_t)r * DMODEL + c) = v;
        }
    }
}

// ---------------------------------------------------------------------------
// Flash attention, fp32. One thread per query row, 128 queries / block.
// K/V staged 32 rows at a time in shared; online softmax in registers.
// Q/K/V layout: [B*S, DMODEL] where head h occupies columns [h*64, h*64+64).
// Mask is int32 (bool widened by harness): nonzero -> masked (score = -1e9).
// ---------------------------------------------------------------------------
#define FBM 128
#define FBN 32

__global__ __launch_bounds__(128) void flash_attn(
    const float* __restrict__ Q, const float* __restrict__ K,
    const float* __restrict__ V, const int* __restrict__ mask,
    float* __restrict__ Ctx)
{
    __shared__ float Ks[FBN][DK];   // 8 KB
    __shared__ float Vs[FBN][DK];   // 8 KB

    const int qt = blockIdx.x;                  // query tile
    const int h  = blockIdx.y;
    const int b  = blockIdx.z;
    const int tid = threadIdx.x;
    const int q  = qt * FBM + tid;              // query index within sequence

    const size_t rowq = ((size_t)(b * SEQ + q)) * DMODEL + h * DK;
    const int* mrow = mask + ((size_t)b * SEQ + q) * SEQ;

    // Load and pre-scale q (scale = 1/sqrt(dk) = 0.125)
    float qr[DK];
#pragma unroll
    for (int d = 0; d < DK; d += 4) {
        float4 v = *(const float4*)(Q + rowq + d);
        qr[d + 0] = v.x * 0.125f; qr[d + 1] = v.y * 0.125f;
        qr[d + 2] = v.z * 0.125f; qr[d + 3] = v.w * 0.125f;
    }

    float m = -INFINITY, l = 0.f;
    float o[DK];
#pragma unroll
    for (int d = 0; d < DK; d++) o[d] = 0.f;

    for (int kt = 0; kt < SEQ; kt += FBN) {
        // Cooperative load of K,V tiles: 32x64 floats each = 512 float4 each
#pragma unroll
        for (int i = 0; i < 4; i++) {
            int f  = i * 128 + tid;            // 0..511
            int r  = f >> 4;                   // key row in tile
            int cg = (f & 15) * 4;             // col group
            size_t gaddr = ((size_t)(b * SEQ + kt + r)) * DMODEL + h * DK + cg;
            *(float4*)(&Ks[r][cg]) = *(const float4*)(K + gaddr);
            *(float4*)(&Vs[r][cg]) = *(const float4*)(V + gaddr);
        }
        __syncthreads();

        // Mask for this thread's row: 32 int32 values as 8x int4 (coalesced 16B)
        int mv[FBN];
#pragma unroll
        for (int w = 0; w < FBN / 4; w++) {
            int4 t = *(const int4*)(mrow + kt + w * 4);
            mv[w * 4 + 0] = t.x; mv[w * 4 + 1] = t.y;
            mv[w * 4 + 2] = t.z; mv[w * 4 + 3] = t.w;
        }

        // Scores (q pre-scaled); masked -> exactly -1e9
        float s[FBN];
#pragma unroll
        for (int j = 0; j < FBN; j++) {
            float s0 = 0.f, s1 = 0.f, s2 = 0.f, s3 = 0.f;
#pragma unroll
            for (int d = 0; d < DK; d += 4) {
                s0 += qr[d + 0] * Ks[j][d + 0];
                s1 += qr[d + 1] * Ks[j][d + 1];
                s2 += qr[d + 2] * Ks[j][d + 2];
                s3 += qr[d + 3] * Ks[j][d + 3];
            }
            float sv = (s0 + s1) + (s2 + s3);
            s[j] = (mv[j] != 0) ? NEGV : sv;
        }

        // Online softmax update
        float tmax = m;
#pragma unroll
        for (int j = 0; j < FBN; j++) tmax = fmaxf(tmax, s[j]);
        float alpha = __expf(m - tmax);     // first tile: exp(-inf)=0
        l *= alpha;
#pragma unroll
        for (int d = 0; d < DK; d++) o[d] *= alpha;

#pragma unroll
        for (int j = 0; j < FBN; j++) {
            float p = __expf(s[j] - tmax);
            l += p;
#pragma unroll
            for (int d = 0; d < DK; d++)
                o[d] += p * Vs[j][d];
        }
        m = tmax;
        __syncthreads();
    }

    float inv = 1.f / l;
#pragma unroll
    for (int d = 0; d < DK; d += 4) {
        float4 v;
        v.x = o[d + 0] * inv; v.y = o[d + 1] * inv;
        v.z = o[d + 2] * inv; v.w = o[d + 3] * inv;
        *(float4*)(Ctx + rowq + d) = v;
    }
}

// ---------------------------------------------------------------------------
// Launch
// ---------------------------------------------------------------------------
extern "C" void kernel_launch(void* const* d_in, const int* in_sizes, int n_in,
                              void* d_out, int out_size)
{
    const float* x    = (const float*)d_in[0];
    const int*   mask = (const int*)d_in[1];
    const float* Wq   = (const float*)d_in[2];
    const float* bq   = (const float*)d_in[3];
    const float* Wk   = (const float*)d_in[4];
    const float* bk   = (const float*)d_in[5];
    const float* Wv   = (const float*)d_in[6];
    const float* bv   = (const float*)d_in[7];
    const float* Wo   = (const float*)d_in[8];
    const float* bo   = (const float*)d_in[9];
    float* out = (float*)d_out;

    float *Qb, *Kb, *Vb, *Cb;
    cudaGetSymbolAddress((void**)&Qb, g_Q);
    cudaGetSymbolAddress((void**)&Kb, g_K);
    cudaGetSymbolAddress((void**)&Vb, g_V);
    cudaGetSymbolAddress((void**)&Cb, g_C);

    dim3 gg(DMODEL / GBN, MTOT / GBM);   // (8, 64)
    gemm_bias<<<gg, 256>>>(x, Wq, bq, Qb);
    gemm_bias<<<gg, 256>>>(x, Wk, bk, Kb);
    gemm_bias<<<gg, 256>>>(x, Wv, bv, Vb);

    dim3 fg(SEQ / FBM, NHEADS, BATCH);   // (16, 16, 4)
    flash_attn<<<fg, 128>>>(Qb, Kb, Vb, mask, Cb);

    gemm_bias<<<gg, 256>>>(Cb, Wo, bo, out);
}

// round 3
// speedup vs baseline: 1.3495x; 1.3495x over previous
#include <cuda_runtime.h>
#include <cstdint>
#include <math.h>

#define BATCH 4
#define SEQ   2048
#define DMODEL 1024
#define NHEADS 16
#define DK    64
#define MTOT  (BATCH*SEQ)      // 8192
#define NEGV  (-1e9f)

// Scratch (alloc-free rule: __device__ globals). 4 x 32 MB.
__device__ float g_Q[MTOT * DMODEL];
__device__ float g_K[MTOT * DMODEL];
__device__ float g_V[MTOT * DMODEL];
__device__ float g_C[MTOT * DMODEL];

__device__ __forceinline__ uint32_t f2tf32(float v) {
    uint32_t t;
    asm("cvt.rna.tf32.f32 %0, %1;" : "=r"(t) : "f"(v));
    return t;
}

__device__ __forceinline__ void mma_tf32(float* c, const uint32_t* a, const uint32_t* b) {
    asm volatile(
        "mma.sync.aligned.m16n8k8.row.col.f32.tf32.tf32.f32 "
        "{%0,%1,%2,%3}, {%4,%5,%6,%7}, {%8,%9}, {%0,%1,%2,%3};"
        : "+f"(c[0]), "+f"(c[1]), "+f"(c[2]), "+f"(c[3])
        : "r"(a[0]), "r"(a[1]), "r"(a[2]), "r"(a[3]), "r"(b[0]), "r"(b[1]));
}

// ---------------------------------------------------------------------------
// GEMM via tf32 mma.sync: Y[M,D] = A[M,D] @ W[D,D] + bias (row-major fp32)
// Block 128x128, K-tile 32, 256 threads (8 warps: 4 along M x 2 along N).
// Warp tile: 32x64 -> 2 m-tiles(16) x 8 n-tiles(8).
// ---------------------------------------------------------------------------
#define TBM 128
#define TBN 128
#define TBK 32

__global__ __launch_bounds__(256) void gemm_tf32(
    const float* __restrict__ A, const float* __restrict__ W,
    const float* __restrict__ bias, float* __restrict__ Y)
{
    // Pads chosen so fragment reads are bank-conflict-free:
    // As bank = (36m+k)%32 = (4m+k)%32 ; lanes (gid,ctid) -> 4*gid+ctid = lane
    // Bs bank = (136k+n)%32 = (8k+n)%32 ; lanes -> 8*ctid+gid distinct
    __shared__ uint32_t As[TBM][36];
    __shared__ uint32_t Bs[TBK][136];

    const int tid  = threadIdx.x;
    const int wid  = tid >> 5;
    const int lane = tid & 31;
    const int gid  = lane >> 2;   // group id 0..7
    const int ctid = lane & 3;    // thread-in-group 0..3
    const int wm   = wid & 3;     // warp row 0..3 (32 rows each)
    const int wn   = wid >> 2;    // warp col 0..1 (64 cols each)

    const int bm = blockIdx.y * TBM;
    const int bn = blockIdx.x * TBN;

    float acc[2][8][4];
#pragma unroll
    for (int i = 0; i < 2; i++)
#pragma unroll
        for (int j = 0; j < 8; j++)
#pragma unroll
            for (int t = 0; t < 4; t++) acc[i][j][t] = 0.f;

    for (int k0 = 0; k0 < DMODEL; k0 += TBK) {
        // A tile: 128 rows x 32 cols = 1024 float4; 4 per thread
#pragma unroll
        for (int i = 0; i < 4; i++) {
            int f  = i * 256 + tid;
            int r  = f >> 3;             // 0..127
            int c4 = (f & 7) * 4;        // 0..28
            float4 v = *(const float4*)(A + (size_t)(bm + r) * DMODEL + k0 + c4);
            As[r][c4 + 0] = f2tf32(v.x); As[r][c4 + 1] = f2tf32(v.y);
            As[r][c4 + 2] = f2tf32(v.z); As[r][c4 + 3] = f2tf32(v.w);
        }
        // W tile: 32 rows x 128 cols = 1024 float4; 4 per thread
#pragma unroll
        for (int i = 0; i < 4; i++) {
            int f  = i * 256 + tid;
            int r  = f >> 5;             // 0..31
            int c4 = (f & 31) * 4;       // 0..124
            float4 v = *(const float4*)(W + (size_t)(k0 + r) * DMODEL + bn + c4);
            Bs[r][c4 + 0] = f2tf32(v.x); Bs[r][c4 + 1] = f2tf32(v.y);
            Bs[r][c4 + 2] = f2tf32(v.z); Bs[r][c4 + 3] = f2tf32(v.w);
        }
        __syncthreads();

#pragma unroll
        for (int ks = 0; ks < 4; ks++) {
            const int kk = ks * 8;
            uint32_t a[2][4], b[8][2];
#pragma unroll
            for (int mt = 0; mt < 2; mt++) {
                int rb = wm * 32 + mt * 16;
                a[mt][0] = As[rb + gid    ][kk + ctid    ];
                a[mt][1] = As[rb + gid + 8][kk + ctid    ];
                a[mt][2] = As[rb + gid    ][kk + ctid + 4];
                a[mt][3] = As[rb + gid + 8][kk + ctid + 4];
            }
#pragma unroll
            for (int nt = 0; nt < 8; nt++) {
                int nb = wn * 64 + nt * 8;
                b[nt][0] = Bs[kk + ctid    ][nb + gid];
                b[nt][1] = Bs[kk + ctid + 4][nb + gid];
            }
#pragma unroll
            for (int mt = 0; mt < 2; mt++)
#pragma unroll
                for (int nt = 0; nt < 8; nt++)
                    mma_tf32(acc[mt][nt], a[mt], b[nt]);
        }
        __syncthreads();
    }

    // Epilogue: c0 (gid, 2c), c1 (gid, 2c+1), c2 (gid+8, 2c), c3 (gid+8, 2c+1)
#pragma unroll
    for (int nt = 0; nt < 8; nt++) {
        int c = bn + wn * 64 + nt * 8 + ctid * 2;
        float b0 = __ldg(bias + c);
        float b1 = __ldg(bias + c + 1);
#pragma unroll
        for (int mt = 0; mt < 2; mt++) {
            int r0 = bm + wm * 32 + mt * 16 + gid;
            float2 v0, v1;
            v0.x = acc[mt][nt][0] + b0; v0.y = acc[mt][nt][1] + b1;
            v1.x = acc[mt][nt][2] + b0; v1.y = acc[mt][nt][3] + b1;
            *(float2*)(Y + (size_t)r0 * DMODEL + c)       = v0;
            *(float2*)(Y + (size_t)(r0 + 8) * DMODEL + c) = v1;
        }
    }
}

// ---------------------------------------------------------------------------
// Flash attention, fp32 scalar with float4 shared reads (broadcast LDS.128).
// One thread per query row, 128 queries / block. Mask int32: nonzero -> -1e9.
// ---------------------------------------------------------------------------
#define FBM 128
#define FBN 32

__global__ __launch_bounds__(128) void flash_attn(
    const float* __restrict__ Q, const float* __restrict__ K,
    const float* __restrict__ V, const int* __restrict__ mask,
    float* __restrict__ Ctx)
{
    __shared__ __align__(16) float Ks[FBN][DK];   // 8 KB
    __shared__ __align__(16) float Vs[FBN][DK];   // 8 KB

    const int qt = blockIdx.x;
    const int h  = blockIdx.y;
    const int b  = blockIdx.z;
    const int tid = threadIdx.x;
    const int q  = qt * FBM + tid;

    const size_t rowq = ((size_t)(b * SEQ + q)) * DMODEL + h * DK;
    const int* mrow = mask + ((size_t)b * SEQ + q) * SEQ;

    float qr[DK];
#pragma unroll
    for (int d = 0; d < DK; d += 4) {
        float4 v = *(const float4*)(Q + rowq + d);
        qr[d + 0] = v.x * 0.125f; qr[d + 1] = v.y * 0.125f;
        qr[d + 2] = v.z * 0.125f; qr[d + 3] = v.w * 0.125f;
    }

    float m = -INFINITY, l = 0.f;
    float o[DK];
#pragma unroll
    for (int d = 0; d < DK; d++) o[d] = 0.f;

    for (int kt = 0; kt < SEQ; kt += FBN) {
#pragma unroll
        for (int i = 0; i < 4; i++) {
            int f  = i * 128 + tid;
            int r  = f >> 4;
            int cg = (f & 15) * 4;
            size_t gaddr = ((size_t)(b * SEQ + kt + r)) * DMODEL + h * DK + cg;
            *(float4*)(&Ks[r][cg]) = *(const float4*)(K + gaddr);
            *(float4*)(&Vs[r][cg]) = *(const float4*)(V + gaddr);
        }
        __syncthreads();

        int mv[FBN];
#pragma unroll
        for (int w = 0; w < FBN / 4; w++) {
            int4 t = *(const int4*)(mrow + kt + w * 4);
            mv[w * 4 + 0] = t.x; mv[w * 4 + 1] = t.y;
            mv[w * 4 + 2] = t.z; mv[w * 4 + 3] = t.w;
        }

        float s[FBN];
#pragma unroll
        for (int j = 0; j < FBN; j++) {
            const float4* k4 = (const float4*)(&Ks[j][0]);
            float s0 = 0.f, s1 = 0.f, s2 = 0.f, s3 = 0.f;
#pragma unroll
            for (int dd = 0; dd < DK / 4; dd++) {
                float4 kv = k4[dd];
                s0 += qr[4 * dd + 0] * kv.x;
                s1 += qr[4 * dd + 1] * kv.y;
                s2 += qr[4 * dd + 2] * kv.z;
                s3 += qr[4 * dd + 3] * kv.w;
            }
            float sv = (s0 + s1) + (s2 + s3);
            s[j] = (mv[j] != 0) ? NEGV : sv;
        }

        float tmax = m;
#pragma unroll
        for (int j = 0; j < FBN; j++) tmax = fmaxf(tmax, s[j]);
        float alpha = __expf(m - tmax);
        l *= alpha;
#pragma unroll
        for (int d = 0; d < DK; d++) o[d] *= alpha;

#pragma unroll
        for (int j = 0; j < FBN; j++) {
            float p = __expf(s[j] - tmax);
            l += p;
            const float4* v4 = (const float4*)(&Vs[j][0]);
#pragma unroll
            for (int dd = 0; dd < DK / 4; dd++) {
                float4 vv = v4[dd];
                o[4 * dd + 0] += p * vv.x;
                o[4 * dd + 1] += p * vv.y;
                o[4 * dd + 2] += p * vv.z;
                o[4 * dd + 3] += p * vv.w;
            }
        }
        m = tmax;
        __syncthreads();
    }

    float inv = 1.f / l;
#pragma unroll
    for (int d = 0; d < DK; d += 4) {
        float4 v;
        v.x = o[d + 0] * inv; v.y = o[d + 1] * inv;
        v.z = o[d + 2] * inv; v.w = o[d + 3] * inv;
        *(float4*)(Ctx + rowq + d) = v;
    }
}

// ---------------------------------------------------------------------------
// Launch
// ---------------------------------------------------------------------------
extern "C" void kernel_launch(void* const* d_in, const int* in_sizes, int n_in,
                              void* d_out, int out_size)
{
    const float* x    = (const float*)d_in[0];
    const int*   mask = (const int*)d_in[1];
    const float* Wq   = (const float*)d_in[2];
    const float* bq   = (const float*)d_in[3];
    const float* Wk   = (const float*)d_in[4];
    const float* bk   = (const float*)d_in[5];
    const float* Wv   = (const float*)d_in[6];
    const float* bv   = (const float*)d_in[7];
    const float* Wo   = (const float*)d_in[8];
    const float* bo   = (const float*)d_in[9];
    float* out = (float*)d_out;

    float *Qb, *Kb, *Vb, *Cb;
    cudaGetSymbolAddress((void**)&Qb, g_Q);
    cudaGetSymbolAddress((void**)&Kb, g_K);
    cudaGetSymbolAddress((void**)&Vb, g_V);
    cudaGetSymbolAddress((void**)&Cb, g_C);

    dim3 gg(DMODEL / TBN, MTOT / TBM);   // (8, 64)
    gemm_tf32<<<gg, 256>>>(x, Wq, bq, Qb);
    gemm_tf32<<<gg, 256>>>(x, Wk, bk, Kb);
    gemm_tf32<<<gg, 256>>>(x, Wv, bv, Vb);

    dim3 fg(SEQ / FBM, NHEADS, BATCH);   // (16, 16, 4)
    flash_attn<<<fg, 128>>>(Qb, Kb, Vb, mask, Cb);

    gemm_tf32<<<gg, 256>>>(Cb, Wo, bo, out);
}

// round 4
// speedup vs baseline: 3.5448x; 2.6268x over previous
#include <cuda_runtime.h>
#include <cstdint>
#include <math.h>

#define BATCH 4
#define SEQ   2048
#define DMODEL 1024
#define NHEADS 16
#define DK    64
#define MTOT  (BATCH*SEQ)      // 8192
#define NEGV  (-1e9f)

// Scratch (alloc-free rule: __device__ globals). 4 x 32 MB.
__device__ float g_Q[MTOT * DMODEL];
__device__ float g_K[MTOT * DMODEL];
__device__ float g_V[MTOT * DMODEL];
__device__ float g_C[MTOT * DMODEL];

__device__ __forceinline__ uint32_t f2tf32(float v) {
    uint32_t t;
    asm("cvt.rna.tf32.f32 %0, %1;" : "=r"(t) : "f"(v));
    return t;
}

__device__ __forceinline__ void mma_tf32(float* c, const uint32_t* a, const uint32_t* b) {
    asm volatile(
        "mma.sync.aligned.m16n8k8.row.col.f32.tf32.tf32.f32 "
        "{%0,%1,%2,%3}, {%4,%5,%6,%7}, {%8,%9}, {%0,%1,%2,%3};"
        : "+f"(c[0]), "+f"(c[1]), "+f"(c[2]), "+f"(c[3])
        : "r"(a[0]), "r"(a[1]), "r"(a[2]), "r"(a[3]), "r"(b[0]), "r"(b[1]));
}

// ---------------------------------------------------------------------------
// GEMM via tf32 mma.sync: Y[M,D] = A[M,D] @ W[D,D] + bias (row-major fp32)
// Block 128x128, K-tile 32, 256 threads (8 warps: 4 along M x 2 along N).
// ---------------------------------------------------------------------------
#define TBM 128
#define TBN 128
#define TBK 32

__global__ __launch_bounds__(256) void gemm_tf32(
    const float* __restrict__ A, const float* __restrict__ W,
    const float* __restrict__ bias, float* __restrict__ Y)
{
    __shared__ uint32_t As[TBM][36];
    __shared__ uint32_t Bs[TBK][136];

    const int tid  = threadIdx.x;
    const int wid  = tid >> 5;
    const int lane = tid & 31;
    const int gid  = lane >> 2;
    const int ctid = lane & 3;
    const int wm   = wid & 3;
    const int wn   = wid >> 2;

    const int bm = blockIdx.y * TBM;
    const int bn = blockIdx.x * TBN;

    float acc[2][8][4];
#pragma unroll
    for (int i = 0; i < 2; i++)
#pragma unroll
        for (int j = 0; j < 8; j++)
#pragma unroll
            for (int t = 0; t < 4; t++) acc[i][j][t] = 0.f;

    for (int k0 = 0; k0 < DMODEL; k0 += TBK) {
#pragma unroll
        for (int i = 0; i < 4; i++) {
            int f  = i * 256 + tid;
            int r  = f >> 3;
            int c4 = (f & 7) * 4;
            float4 v = *(const float4*)(A + (size_t)(bm + r) * DMODEL + k0 + c4);
            As[r][c4 + 0] = f2tf32(v.x); As[r][c4 + 1] = f2tf32(v.y);
            As[r][c4 + 2] = f2tf32(v.z); As[r][c4 + 3] = f2tf32(v.w);
        }
#pragma unroll
        for (int i = 0; i < 4; i++) {
            int f  = i * 256 + tid;
            int r  = f >> 5;
            int c4 = (f & 31) * 4;
            float4 v = *(const float4*)(W + (size_t)(k0 + r) * DMODEL + bn + c4);
            Bs[r][c4 + 0] = f2tf32(v.x); Bs[r][c4 + 1] = f2tf32(v.y);
            Bs[r][c4 + 2] = f2tf32(v.z); Bs[r][c4 + 3] = f2tf32(v.w);
        }
        __syncthreads();

#pragma unroll
        for (int ks = 0; ks < 4; ks++) {
            const int kk = ks * 8;
            uint32_t a[2][4], b[8][2];
#pragma unroll
            for (int mt = 0; mt < 2; mt++) {
                int rb = wm * 32 + mt * 16;
                a[mt][0] = As[rb + gid    ][kk + ctid    ];
                a[mt][1] = As[rb + gid + 8][kk + ctid    ];
                a[mt][2] = As[rb + gid    ][kk + ctid + 4];
                a[mt][3] = As[rb + gid + 8][kk + ctid + 4];
            }
#pragma unroll
            for (int nt = 0; nt < 8; nt++) {
                int nb = wn * 64 + nt * 8;
                b[nt][0] = Bs[kk + ctid    ][nb + gid];
                b[nt][1] = Bs[kk + ctid + 4][nb + gid];
            }
#pragma unroll
            for (int mt = 0; mt < 2; mt++)
#pragma unroll
                for (int nt = 0; nt < 8; nt++)
                    mma_tf32(acc[mt][nt], a[mt], b[nt]);
        }
        __syncthreads();
    }

#pragma unroll
    for (int nt = 0; nt < 8; nt++) {
        int c = bn + wn * 64 + nt * 8 + ctid * 2;
        float b0 = __ldg(bias + c);
        float b1 = __ldg(bias + c + 1);
#pragma unroll
        for (int mt = 0; mt < 2; mt++) {
            int r0 = bm + wm * 32 + mt * 16 + gid;
            float2 v0, v1;
            v0.x = acc[mt][nt][0] + b0; v0.y = acc[mt][nt][1] + b1;
            v1.x = acc[mt][nt][2] + b0; v1.y = acc[mt][nt][3] + b1;
            *(float2*)(Y + (size_t)r0 * DMODEL + c)       = v0;
            *(float2*)(Y + (size_t)(r0 + 8) * DMODEL + c) = v1;
        }
    }
}

// ---------------------------------------------------------------------------
// Flash attention via tf32 mma.sync.
// Block: 128 queries x 1 head; 4 warps x 32 queries (2 m-tiles of 16).
// Key tile 32. S = Q K^T on tensor cores; P through per-warp smem; P V on
// tensor cores. Online softmax on C-fragments with quad shuffles.
// ---------------------------------------------------------------------------
#define FQ  128
#define FKT 32
#define KSP 68   // Ks pitch (words): bank (4j+d)%32 -> frag reads = lane
#define VSP 72   // Vs pitch (words): bank (8k+n)%32 -> frag reads distinct
#define PSP 36   // Ps pitch (words): bank (4m+k)%32 -> A-frag reads = lane

__global__ __launch_bounds__(128) void flash_mma(
    const float* __restrict__ Q, const float* __restrict__ K,
    const float* __restrict__ V, const int* __restrict__ mask,
    float* __restrict__ Ctx)
{
    __shared__ __align__(16) uint32_t s_kv[FKT * KSP + FKT * VSP]; // 17.9 KB
    __shared__ __align__(16) uint32_t Ps[4][32][PSP];              // 18.4 KB
#define KS(r, c) s_kv[(r) * KSP + (c)]
#define VS(r, c) s_kv[FKT * KSP + (r) * VSP + (c)]

    const int tid  = threadIdx.x;
    const int w    = tid >> 5;
    const int lane = tid & 31;
    const int gid  = lane >> 2;
    const int ctid = lane & 3;

    const int qt = blockIdx.x;
    const int h  = blockIdx.y;
    const int b  = blockIdx.z;
    const int qbase = qt * FQ;
    const int wq    = w * 32;          // warp's query offset within block

    // ---- Build Q fragments (held in registers for the whole kernel) ----
    float* qstage = (float*)s_kv;      // 64 x 64 staging (16 KB, fits in s_kv)
    uint32_t qa[2][8][4];
#pragma unroll
    for (int half = 0; half < 2; half++) {
        __syncthreads();
#pragma unroll
        for (int i = 0; i < 8; i++) {
            int f  = i * 128 + tid;
            int r  = f >> 4;
            int cg = (f & 15) * 4;
            float4 v = *(const float4*)(
                Q + ((size_t)(b * SEQ + qbase + half * 64 + r)) * DMODEL + h * DK + cg);
            qstage[r * 64 + cg + 0] = v.x * 0.125f;
            qstage[r * 64 + cg + 1] = v.y * 0.125f;
            qstage[r * 64 + cg + 2] = v.z * 0.125f;
            qstage[r * 64 + cg + 3] = v.w * 0.125f;
        }
        __syncthreads();
        if ((w >> 1) == half) {
            int lrow = (w & 1) * 32;
#pragma unroll
            for (int mt = 0; mt < 2; mt++)
#pragma unroll
                for (int ks = 0; ks < 8; ks++) {
                    int rb = lrow + mt * 16;
                    qa[mt][ks][0] = f2tf32(qstage[(rb + gid    ) * 64 + ks * 8 + ctid    ]);
                    qa[mt][ks][1] = f2tf32(qstage[(rb + gid + 8) * 64 + ks * 8 + ctid    ]);
                    qa[mt][ks][2] = f2tf32(qstage[(rb + gid    ) * 64 + ks * 8 + ctid + 4]);
                    qa[mt][ks][3] = f2tf32(qstage[(rb + gid + 8) * 64 + ks * 8 + ctid + 4]);
                }
        }
    }
    __syncthreads();

    // ---- Online-softmax state ----
    float m_[4], l_[4];                 // rows: [mt*2 + half]
#pragma unroll
    for (int i = 0; i < 4; i++) { m_[i] = -INFINITY; l_[i] = 0.f; }
    float o_[2][8][4];
#pragma unroll
    for (int mt = 0; mt < 2; mt++)
#pragma unroll
        for (int nt = 0; nt < 8; nt++)
#pragma unroll
            for (int t = 0; t < 4; t++) o_[mt][nt][t] = 0.f;

    for (int kt = 0; kt < SEQ; kt += FKT) {
        // Load K,V tiles (32x64), convert to tf32, padded smem
#pragma unroll
        for (int i = 0; i < 4; i++) {
            int f  = i * 128 + tid;
            int r  = f >> 4;
            int cg = (f & 15) * 4;
            size_t ga = ((size_t)(b * SEQ + kt + r)) * DMODEL + h * DK + cg;
            float4 kv = *(const float4*)(K + ga);
            KS(r, cg + 0) = f2tf32(kv.x); KS(r, cg + 1) = f2tf32(kv.y);
            KS(r, cg + 2) = f2tf32(kv.z); KS(r, cg + 3) = f2tf32(kv.w);
            float4 vv = *(const float4*)(V + ga);
            VS(r, cg + 0) = f2tf32(vv.x); VS(r, cg + 1) = f2tf32(vv.y);
            VS(r, cg + 2) = f2tf32(vv.z); VS(r, cg + 3) = f2tf32(vv.w);
        }
        __syncthreads();

        // ---- S = Q K^T ----
        float s_[2][4][4];
#pragma unroll
        for (int mt = 0; mt < 2; mt++)
#pragma unroll
            for (int nt = 0; nt < 4; nt++)
#pragma unroll
                for (int t = 0; t < 4; t++) s_[mt][nt][t] = 0.f;

#pragma unroll
        for (int ks = 0; ks < 8; ks++) {
            uint32_t bk[4][2];
#pragma unroll
            for (int nt = 0; nt < 4; nt++) {
                bk[nt][0] = KS(nt * 8 + gid, ks * 8 + ctid    );
                bk[nt][1] = KS(nt * 8 + gid, ks * 8 + ctid + 4);
            }
#pragma unroll
            for (int mt = 0; mt < 2; mt++)
#pragma unroll
                for (int nt = 0; nt < 4; nt++)
                    mma_tf32(s_[mt][nt], qa[mt][ks], bk[nt]);
        }

        // ---- mask + online softmax + write P ----
        float alpha_[2][2];
#pragma unroll
        for (int mt = 0; mt < 2; mt++)
#pragma unroll
            for (int half = 0; half < 2; half++) {
                const int ridx = mt * 2 + half;
                const int qrow = qbase + wq + mt * 16 + half * 8 + gid;
                const int* mp  = mask + ((size_t)b * SEQ + qrow) * SEQ + kt;
                float sv[8];
#pragma unroll
                for (int nt = 0; nt < 4; nt++) {
                    int2 mm = __ldg((const int2*)(mp + nt * 8 + 2 * ctid));
                    float v0 = s_[mt][nt][half * 2 + 0];
                    float v1 = s_[mt][nt][half * 2 + 1];
                    sv[nt * 2 + 0] = mm.x ? NEGV : v0;
                    sv[nt * 2 + 1] = mm.y ? NEGV : v1;
                }
                float tmax = sv[0];
#pragma unroll
                for (int j = 1; j < 8; j++) tmax = fmaxf(tmax, sv[j]);
                tmax = fmaxf(tmax, __shfl_xor_sync(0xffffffffu, tmax, 1));
                tmax = fmaxf(tmax, __shfl_xor_sync(0xffffffffu, tmax, 2));
                float newm  = fmaxf(m_[ridx], tmax);
                float alpha = __expf(m_[ridx] - newm);
                m_[ridx] = newm;

                float psum = 0.f;
#pragma unroll
                for (int nt = 0; nt < 4; nt++) {
                    float p0 = __expf(sv[nt * 2 + 0] - newm);
                    float p1 = __expf(sv[nt * 2 + 1] - newm);
                    psum += p0 + p1;
                    uint2 pp; pp.x = f2tf32(p0); pp.y = f2tf32(p1);
                    *(uint2*)&Ps[w][mt * 16 + half * 8 + gid][nt * 8 + 2 * ctid] = pp;
                }
                psum += __shfl_xor_sync(0xffffffffu, psum, 1);
                psum += __shfl_xor_sync(0xffffffffu, psum, 2);
                l_[ridx] = l_[ridx] * alpha + psum;
                alpha_[mt][half] = alpha;
            }

        // rescale O by alpha (c0,c1 -> row gid = half0; c2,c3 -> gid+8 = half1)
#pragma unroll
        for (int mt = 0; mt < 2; mt++)
#pragma unroll
            for (int nt = 0; nt < 8; nt++) {
                o_[mt][nt][0] *= alpha_[mt][0];
                o_[mt][nt][1] *= alpha_[mt][0];
                o_[mt][nt][2] *= alpha_[mt][1];
                o_[mt][nt][3] *= alpha_[mt][1];
            }
        __syncwarp();

        // ---- O += P V ----
#pragma unroll
        for (int kk = 0; kk < 4; kk++) {
            uint32_t av[2][4], bv[8][2];
#pragma unroll
            for (int mt = 0; mt < 2; mt++) {
                av[mt][0] = Ps[w][mt * 16 + gid    ][kk * 8 + ctid    ];
                av[mt][1] = Ps[w][mt * 16 + gid + 8][kk * 8 + ctid    ];
                av[mt][2] = Ps[w][mt * 16 + gid    ][kk * 8 + ctid + 4];
                av[mt][3] = Ps[w][mt * 16 + gid + 8][kk * 8 + ctid + 4];
            }
#pragma unroll
            for (int nt = 0; nt < 8; nt++) {
                bv[nt][0] = VS(kk * 8 + ctid    , nt * 8 + gid);
                bv[nt][1] = VS(kk * 8 + ctid + 4, nt * 8 + gid);
            }
#pragma unroll
            for (int mt = 0; mt < 2; mt++)
#pragma unroll
                for (int nt = 0; nt < 8; nt++)
                    mma_tf32(o_[mt][nt], av[mt], bv[nt]);
        }
        __syncthreads();
    }

    // ---- normalize + store ----
#pragma unroll
    for (int mt = 0; mt < 2; mt++) {
        float inv0 = 1.f / l_[mt * 2 + 0];
        float inv1 = 1.f / l_[mt * 2 + 1];
        size_t r0 = (size_t)(b * SEQ + qbase + wq + mt * 16 + gid);
#pragma unroll
        for (int nt = 0; nt < 8; nt++) {
            int c = h * DK + nt * 8 + 2 * ctid;
            float2 v0, v1;
            v0.x = o_[mt][nt][0] * inv0; v0.y = o_[mt][nt][1] * inv0;
            v1.x = o_[mt][nt][2] * inv1; v1.y = o_[mt][nt][3] * inv1;
            *(float2*)(Ctx + r0 * DMODEL + c)       = v0;
            *(float2*)(Ctx + (r0 + 8) * DMODEL + c) = v1;
        }
    }
#undef KS
#undef VS
}

// ---------------------------------------------------------------------------
// Launch
// ---------------------------------------------------------------------------
extern "C" void kernel_launch(void* const* d_in, const int* in_sizes, int n_in,
                              void* d_out, int out_size)
{
    const float* x    = (const float*)d_in[0];
    const int*   mask = (const int*)d_in[1];
    const float* Wq   = (const float*)d_in[2];
    const float* bq   = (const float*)d_in[3];
    const float* Wk   = (const float*)d_in[4];
    const float* bk   = (const float*)d_in[5];
    const float* Wv   = (const float*)d_in[6];
    const float* bv   = (const float*)d_in[7];
    const float* Wo   = (const float*)d_in[8];
    const float* bo   = (const float*)d_in[9];
    float* out = (float*)d_out;

    float *Qb, *Kb, *Vb, *Cb;
    cudaGetSymbolAddress((void**)&Qb, g_Q);
    cudaGetSymbolAddress((void**)&Kb, g_K);
    cudaGetSymbolAddress((void**)&Vb, g_V);
    cudaGetSymbolAddress((void**)&Cb, g_C);

    dim3 gg(DMODEL / TBN, MTOT / TBM);   // (8, 64)
    gemm_tf32<<<gg, 256>>>(x, Wq, bq, Qb);
    gemm_tf32<<<gg, 256>>>(x, Wk, bk, Kb);
    gemm_tf32<<<gg, 256>>>(x, Wv, bv, Vb);

    dim3 fg(SEQ / FQ, NHEADS, BATCH);    // (16, 16, 4)
    flash_mma<<<fg, 128>>>(Qb, Kb, Vb, mask, Cb);

    gemm_tf32<<<gg, 256>>>(Cb, Wo, bo, out);
}

// round 6
// speedup vs baseline: 4.2057x; 1.1864x over previous
#include <cuda_runtime.h>
#include <cuda_fp16.h>
#include <cstdint>
#include <math.h>

#define BATCH 4
#define SEQ   2048
#define DMODEL 1024
#define NHEADS 16
#define DK    64
#define MTOT  (BATCH*SEQ)      // 8192
#define NEGV  (-1e9f)

// Scratch (alloc-free rule: __device__ globals).
__device__ __half g_Qh[MTOT * DMODEL];   // pre-scaled by 0.125
__device__ __half g_Kh[MTOT * DMODEL];
__device__ __half g_Vh[MTOT * DMODEL];
__device__ float  g_C [MTOT * DMODEL];

__device__ __forceinline__ uint32_t f2tf32(float v) {
    uint32_t t;
    asm("cvt.rna.tf32.f32 %0, %1;" : "=r"(t) : "f"(v));
    return t;
}

// Pack two floats into one register as f16x2 (round-to-nearest-even).
__device__ __forceinline__ uint32_t pack_f16x2(float lo, float hi) {
    uint32_t r;
    asm("cvt.rn.f16x2.f32 %0, %1, %2;" : "=r"(r) : "f"(hi), "f"(lo));
    return r;
}

__device__ __forceinline__ void mma_tf32(float* c, const uint32_t* a, const uint32_t* b) {
    asm volatile(
        "mma.sync.aligned.m16n8k8.row.col.f32.tf32.tf32.f32 "
        "{%0,%1,%2,%3}, {%4,%5,%6,%7}, {%8,%9}, {%0,%1,%2,%3};"
        : "+f"(c[0]), "+f"(c[1]), "+f"(c[2]), "+f"(c[3])
        : "r"(a[0]), "r"(a[1]), "r"(a[2]), "r"(a[3]), "r"(b[0]), "r"(b[1]));
}

__device__ __forceinline__ void mma_f16(float* c, const uint32_t* a, const uint32_t* b) {
    asm volatile(
        "mma.sync.aligned.m16n8k16.row.col.f32.f16.f16.f32 "
        "{%0,%1,%2,%3}, {%4,%5,%6,%7}, {%8,%9}, {%0,%1,%2,%3};"
        : "+f"(c[0]), "+f"(c[1]), "+f"(c[2]), "+f"(c[3])
        : "r"(a[0]), "r"(a[1]), "r"(a[2]), "r"(a[3]), "r"(b[0]), "r"(b[1]));
}

// ---------------------------------------------------------------------------
// tf32 GEMM core (128x128x32, 256 threads). Two epilogues: fp32 and fp16.
// ---------------------------------------------------------------------------
#define TBM 128
#define TBN 128
#define TBK 32

template <typename OutT>
__global__ __launch_bounds__(256) void gemm_tf32_t(
    const float* __restrict__ A, const float* __restrict__ W,
    const float* __restrict__ bias, OutT* __restrict__ Y, float oscale)
{
    __shared__ uint32_t As[TBM][36];
    __shared__ uint32_t Bs[TBK][136];

    const int tid  = threadIdx.x;
    const int wid  = tid >> 5;
    const int lane = tid & 31;
    const int gid  = lane >> 2;
    const int ctid = lane & 3;
    const int wm   = wid & 3;
    const int wn   = wid >> 2;

    const int bm = blockIdx.y * TBM;
    const int bn = blockIdx.x * TBN;

    float acc[2][8][4];
#pragma unroll
    for (int i = 0; i < 2; i++)
#pragma unroll
        for (int j = 0; j < 8; j++)
#pragma unroll
            for (int t = 0; t < 4; t++) acc[i][j][t] = 0.f;

    for (int k0 = 0; k0 < DMODEL; k0 += TBK) {
#pragma unroll
        for (int i = 0; i < 4; i++) {
            int f  = i * 256 + tid;
            int r  = f >> 3;
            int c4 = (f & 7) * 4;
            float4 v = *(const float4*)(A + (size_t)(bm + r) * DMODEL + k0 + c4);
            As[r][c4 + 0] = f2tf32(v.x); As[r][c4 + 1] = f2tf32(v.y);
            As[r][c4 + 2] = f2tf32(v.z); As[r][c4 + 3] = f2tf32(v.w);
        }
#pragma unroll
        for (int i = 0; i < 4; i++) {
            int f  = i * 256 + tid;
            int r  = f >> 5;
            int c4 = (f & 31) * 4;
            float4 v = *(const float4*)(W + (size_t)(k0 + r) * DMODEL + bn + c4);
            Bs[r][c4 + 0] = f2tf32(v.x); Bs[r][c4 + 1] = f2tf32(v.y);
            Bs[r][c4 + 2] = f2tf32(v.z); Bs[r][c4 + 3] = f2tf32(v.w);
        }
        __syncthreads();

#pragma unroll
        for (int ks = 0; ks < 4; ks++) {
            const int kk = ks * 8;
            uint32_t a[2][4], b[8][2];
#pragma unroll
            for (int mt = 0; mt < 2; mt++) {
                int rb = wm * 32 + mt * 16;
                a[mt][0] = As[rb + gid    ][kk + ctid    ];
                a[mt][1] = As[rb + gid + 8][kk + ctid    ];
                a[mt][2] = As[rb + gid    ][kk + ctid + 4];
                a[mt][3] = As[rb + gid + 8][kk + ctid + 4];
            }
#pragma unroll
            for (int nt = 0; nt < 8; nt++) {
                int nb = wn * 64 + nt * 8;
                b[nt][0] = Bs[kk + ctid    ][nb + gid];
                b[nt][1] = Bs[kk + ctid + 4][nb + gid];
            }
#pragma unroll
            for (int mt = 0; mt < 2; mt++)
#pragma unroll
                for (int nt = 0; nt < 8; nt++)
                    mma_tf32(acc[mt][nt], a[mt], b[nt]);
        }
        __syncthreads();
    }

#pragma unroll
    for (int nt = 0; nt < 8; nt++) {
        int c = bn + wn * 64 + nt * 8 + ctid * 2;
        float b0 = __ldg(bias + c);
        float b1 = __ldg(bias + c + 1);
#pragma unroll
        for (int mt = 0; mt < 2; mt++) {
            int r0 = bm + wm * 32 + mt * 16 + gid;
            float v00 = (acc[mt][nt][0] + b0) * oscale;
            float v01 = (acc[mt][nt][1] + b1) * oscale;
            float v10 = (acc[mt][nt][2] + b0) * oscale;
            float v11 = (acc[mt][nt][3] + b1) * oscale;
            if constexpr (sizeof(OutT) == 4) {
                float2 p0 = make_float2(v00, v01);
                float2 p1 = make_float2(v10, v11);
                *(float2*)((float*)Y + (size_t)r0 * DMODEL + c)       = p0;
                *(float2*)((float*)Y + (size_t)(r0 + 8) * DMODEL + c) = p1;
            } else {
                uint32_t p0 = pack_f16x2(v00, v01);
                uint32_t p1 = pack_f16x2(v10, v11);
                *(uint32_t*)((__half*)Y + (size_t)r0 * DMODEL + c)       = p0;
                *(uint32_t*)((__half*)Y + (size_t)(r0 + 8) * DMODEL + c) = p1;
            }
        }
    }
}

// ---------------------------------------------------------------------------
// Flash attention, fp16 m16n8k16, FA2-style register P-reuse.
// Block: 256 threads = 8 warps; 128 queries per block (16 per warp).
// Key tile 64. K smem [key][d] pad 72 halfs; V smem transposed [d][key] pad 72.
// ---------------------------------------------------------------------------
#define FKT 64
#define KVP 72   // half pitch; word pitch 36 === 4 (mod 32) -> conflict-free frags

__global__ __launch_bounds__(256) void flash_f16(
    const __half* __restrict__ Qh, const __half* __restrict__ Kh,
    const __half* __restrict__ Vh, const int* __restrict__ mask,
    float* __restrict__ Ctx)
{
    __shared__ __align__(16) __half Ks[FKT * KVP];   // 9 KB
    __shared__ __align__(16) __half Vt[DK  * KVP];   // 9 KB

    const int tid  = threadIdx.x;
    const int w    = tid >> 5;
    const int lane = tid & 31;
    const int gid  = lane >> 2;
    const int ctid = lane & 3;

    const int h  = blockIdx.y;
    const int b  = blockIdx.z;
    const int qb = blockIdx.x * 128 + w * 16;        // seq-local query base

    // Q fragments: held in registers for the whole kernel (Q pre-scaled by 1/8)
    uint32_t qa[4][4];
    {
        const __half* q0 = Qh + (size_t)(b * SEQ + qb + gid    ) * DMODEL + h * DK;
        const __half* q1 = Qh + (size_t)(b * SEQ + qb + gid + 8) * DMODEL + h * DK;
#pragma unroll
        for (int t = 0; t < 4; t++) {
            qa[t][0] = *(const uint32_t*)(q0 + 16 * t + 2 * ctid);
            qa[t][1] = *(const uint32_t*)(q1 + 16 * t + 2 * ctid);
            qa[t][2] = *(const uint32_t*)(q0 + 16 * t + 2 * ctid + 8);
            qa[t][3] = *(const uint32_t*)(q1 + 16 * t + 2 * ctid + 8);
        }
    }

    float m0 = -INFINITY, m1 = -INFINITY, l0 = 0.f, l1 = 0.f;
    float o[8][4];
#pragma unroll
    for (int nd = 0; nd < 8; nd++)
#pragma unroll
        for (int t = 0; t < 4; t++) o[nd][t] = 0.f;

    const int* mrow0 = mask + ((size_t)b * SEQ + qb + gid    ) * SEQ;
    const int* mrow1 = mask + ((size_t)b * SEQ + qb + gid + 8) * SEQ;

    for (int kt = 0; kt < SEQ; kt += FKT) {
        __syncthreads();
        // K tile: 64x64 halfs = 512 uint4 ; 2 per thread
#pragma unroll
        for (int i = 0; i < 2; i++) {
            int f  = i * 256 + tid;
            int r  = f >> 3;
            int c8 = (f & 7) * 8;
            *(uint4*)(&Ks[r * KVP + c8]) =
                *(const uint4*)(Kh + (size_t)(b * SEQ + kt + r) * DMODEL + h * DK + c8);
        }
        // V tile transposed: each thread 4 iters x (4 halfs of one key row)
#pragma unroll
        for (int i = 0; i < 4; i++) {
            int f  = i * 256 + tid;
            int r  = f >> 4;              // key 0..63
            int cg = (f & 15) * 4;        // d col 0..60
            const __half* src = Vh + (size_t)(b * SEQ + kt + r) * DMODEL + h * DK + cg;
            __half2 v01 = *(const __half2*)(src);
            __half2 v23 = *(const __half2*)(src + 2);
            Vt[(cg + 0) * KVP + r] = __low2half(v01);
            Vt[(cg + 1) * KVP + r] = __high2half(v01);
            Vt[(cg + 2) * KVP + r] = __low2half(v23);
            Vt[(cg + 3) * KVP + r] = __high2half(v23);
        }
        __syncthreads();

        // ---- S = Q K^T : 8 n-tiles x 4 k-steps ----
        float sc[8][4];
#pragma unroll
        for (int nt = 0; nt < 8; nt++) {
#pragma unroll
            for (int t4 = 0; t4 < 4; t4++) sc[nt][t4] = 0.f;
            const __half* kr = &Ks[(nt * 8 + gid) * KVP];
#pragma unroll
            for (int t = 0; t < 4; t++) {
                uint32_t bk[2];
                bk[0] = *(const uint32_t*)(kr + 16 * t + 2 * ctid);
                bk[1] = *(const uint32_t*)(kr + 16 * t + 2 * ctid + 8);
                mma_f16(sc[nt], qa[t], bk);
            }
        }

        // ---- mask (apply in place) ----
#pragma unroll
        for (int nt = 0; nt < 8; nt++) {
            int koff = kt + nt * 8 + 2 * ctid;
            int2 mm0 = __ldg((const int2*)(mrow0 + koff));
            int2 mm1 = __ldg((const int2*)(mrow1 + koff));
            if (mm0.x) sc[nt][0] = NEGV;
            if (mm0.y) sc[nt][1] = NEGV;
            if (mm1.x) sc[nt][2] = NEGV;
            if (mm1.y) sc[nt][3] = NEGV;
        }

        // ---- online softmax ----
        float t0 = sc[0][0], t1 = sc[0][2];
#pragma unroll
        for (int nt = 0; nt < 8; nt++) {
            t0 = fmaxf(t0, fmaxf(sc[nt][0], sc[nt][1]));
            t1 = fmaxf(t1, fmaxf(sc[nt][2], sc[nt][3]));
        }
        t0 = fmaxf(t0, __shfl_xor_sync(0xffffffffu, t0, 1));
        t0 = fmaxf(t0, __shfl_xor_sync(0xffffffffu, t0, 2));
        t1 = fmaxf(t1, __shfl_xor_sync(0xffffffffu, t1, 1));
        t1 = fmaxf(t1, __shfl_xor_sync(0xffffffffu, t1, 2));
        float nm0 = fmaxf(m0, t0), nm1 = fmaxf(m1, t1);
        float al0 = __expf(m0 - nm0), al1 = __expf(m1 - nm1);
        m0 = nm0; m1 = nm1;

        // p = exp(s - m), packed straight into PV A-fragments
        uint32_t pa[4][4];
        float ps0 = 0.f, ps1 = 0.f;
#pragma unroll
        for (int nt = 0; nt < 8; nt++) {
            float p00 = __expf(sc[nt][0] - nm0);
            float p01 = __expf(sc[nt][1] - nm0);
            float p10 = __expf(sc[nt][2] - nm1);
            float p11 = __expf(sc[nt][3] - nm1);
            ps0 += p00 + p01;
            ps1 += p10 + p11;
            int tt = nt >> 1;
            int hi = (nt & 1) ? 2 : 0;   // a0/a1 for keys k<8, a2/a3 for k>=8
            pa[tt][hi + 0] = pack_f16x2(p00, p01);
            pa[tt][hi + 1] = pack_f16x2(p10, p11);
        }
        ps0 += __shfl_xor_sync(0xffffffffu, ps0, 1);
        ps0 += __shfl_xor_sync(0xffffffffu, ps0, 2);
        ps1 += __shfl_xor_sync(0xffffffffu, ps1, 1);
        ps1 += __shfl_xor_sync(0xffffffffu, ps1, 2);
        l0 = l0 * al0 + ps0;
        l1 = l1 * al1 + ps1;

        // ---- O = O*alpha + P V ----
#pragma unroll
        for (int nd = 0; nd < 8; nd++) {
            o[nd][0] *= al0; o[nd][1] *= al0;
            o[nd][2] *= al1; o[nd][3] *= al1;
        }
#pragma unroll
        for (int tt = 0; tt < 4; tt++) {
#pragma unroll
            for (int nd = 0; nd < 8; nd++) {
                const __half* vr = &Vt[(nd * 8 + gid) * KVP];
                uint32_t bv[2];
                bv[0] = *(const uint32_t*)(vr + 16 * tt + 2 * ctid);
                bv[1] = *(const uint32_t*)(vr + 16 * tt + 2 * ctid + 8);
                mma_f16(o[nd], pa[tt], bv);
            }
        }
    }

    // ---- normalize + store ----
    float i0 = 1.f / l0, i1 = 1.f / l1;
    size_t r0 = (size_t)(b * SEQ + qb + gid);
#pragma unroll
    for (int nd = 0; nd < 8; nd++) {
        int c = h * DK + nd * 8 + 2 * ctid;
        float2 v0, v1;
        v0.x = o[nd][0] * i0; v0.y = o[nd][1] * i0;
        v1.x = o[nd][2] * i1; v1.y = o[nd][3] * i1;
        *(float2*)(Ctx + r0 * DMODEL + c)       = v0;
        *(float2*)(Ctx + (r0 + 8) * DMODEL + c) = v1;
    }
}

// ---------------------------------------------------------------------------
// Launch
// ---------------------------------------------------------------------------
extern "C" void kernel_launch(void* const* d_in, const int* in_sizes, int n_in,
                              void* d_out, int out_size)
{
    const float* x    = (const float*)d_in[0];
    const int*   mask = (const int*)d_in[1];
    const float* Wq   = (const float*)d_in[2];
    const float* bq   = (const float*)d_in[3];
    const float* Wk   = (const float*)d_in[4];
    const float* bk   = (const float*)d_in[5];
    const float* Wv   = (const float*)d_in[6];
    const float* bv   = (const float*)d_in[7];
    const float* Wo   = (const float*)d_in[8];
    const float* bo   = (const float*)d_in[9];
    float* out = (float*)d_out;

    __half *Qh, *Kh, *Vh; float* Cb;
    cudaGetSymbolAddress((void**)&Qh, g_Qh);
    cudaGetSymbolAddress((void**)&Kh, g_Kh);
    cudaGetSymbolAddress((void**)&Vh, g_Vh);
    cudaGetSymbolAddress((void**)&Cb, g_C);

    dim3 gg(DMODEL / TBN, MTOT / TBM);   // (8, 64)
    gemm_tf32_t<__half><<<gg, 256>>>(x, Wq, bq, Qh, 0.125f);  // Q pre-scaled
    gemm_tf32_t<__half><<<gg, 256>>>(x, Wk, bk, Kh, 1.0f);
    gemm_tf32_t<__half><<<gg, 256>>>(x, Wv, bv, Vh, 1.0f);

    dim3 fg(SEQ / 128, NHEADS, BATCH);   // (16, 16, 4)
    flash_f16<<<fg, 256>>>(Qh, Kh, Vh, mask, Cb);

    gemm_tf32_t<float><<<gg, 256>>>(Cb, Wo, bo, out, 1.0f);
}

// round 7
// speedup vs baseline: 4.4645x; 1.0615x over previous
#include <cuda_runtime.h>
#include <cuda_fp16.h>
#include <cstdint>
#include <math.h>

#define BATCH 4
#define SEQ   2048
#define DMODEL 1024
#define NHEADS 16
#define DK    64
#define MTOT  (BATCH*SEQ)      // 8192
#define NEGV  (-1e9f)
#define MW    (SEQ/32)         // 64 mask words per row

// Scratch (alloc-free rule: __device__ globals).
__device__ __half   g_Qh[MTOT * DMODEL];   // pre-scaled by 0.125
__device__ __half   g_Kh[MTOT * DMODEL];
__device__ __half   g_Vh[MTOT * DMODEL];
__device__ float    g_C [MTOT * DMODEL];
__device__ uint32_t g_Mb[BATCH * SEQ * MW];  // bit-packed mask (2 MB)

__device__ __forceinline__ uint32_t f2tf32(float v) {
    uint32_t t;
    asm("cvt.rna.tf32.f32 %0, %1;" : "=r"(t) : "f"(v));
    return t;
}

__device__ __forceinline__ uint32_t pack_f16x2(float lo, float hi) {
    uint32_t r;
    asm("cvt.rn.f16x2.f32 %0, %1, %2;" : "=r"(r) : "f"(hi), "f"(lo));
    return r;
}

__device__ __forceinline__ uint32_t sptr(const void* p) {
    return (uint32_t)__cvta_generic_to_shared(p);
}

__device__ __forceinline__ void ldsm_x4(uint32_t* r, uint32_t addr) {
    asm volatile("ldmatrix.sync.aligned.m8n8.x4.shared.b16 {%0,%1,%2,%3}, [%4];"
                 : "=r"(r[0]), "=r"(r[1]), "=r"(r[2]), "=r"(r[3]) : "r"(addr));
}

__device__ __forceinline__ void ldsm_x4_t(uint32_t* r, uint32_t addr) {
    asm volatile("ldmatrix.sync.aligned.m8n8.x4.trans.shared.b16 {%0,%1,%2,%3}, [%4];"
                 : "=r"(r[0]), "=r"(r[1]), "=r"(r[2]), "=r"(r[3]) : "r"(addr));
}

__device__ __forceinline__ void mma_tf32(float* c, const uint32_t* a, const uint32_t* b) {
    asm volatile(
        "mma.sync.aligned.m16n8k8.row.col.f32.tf32.tf32.f32 "
        "{%0,%1,%2,%3}, {%4,%5,%6,%7}, {%8,%9}, {%0,%1,%2,%3};"
        : "+f"(c[0]), "+f"(c[1]), "+f"(c[2]), "+f"(c[3])
        : "r"(a[0]), "r"(a[1]), "r"(a[2]), "r"(a[3]), "r"(b[0]), "r"(b[1]));
}

__device__ __forceinline__ void mma_f16(float* c, const uint32_t* a, const uint32_t* b) {
    asm volatile(
        "mma.sync.aligned.m16n8k16.row.col.f32.f16.f16.f32 "
        "{%0,%1,%2,%3}, {%4,%5,%6,%7}, {%8,%9}, {%0,%1,%2,%3};"
        : "+f"(c[0]), "+f"(c[1]), "+f"(c[2]), "+f"(c[3])
        : "r"(a[0]), "r"(a[1]), "r"(a[2]), "r"(a[3]), "r"(b[0]), "r"(b[1]));
}

// ---------------------------------------------------------------------------
// Bit-pack the int32 mask: one warp -> one uint32 word (32 keys).
// ---------------------------------------------------------------------------
__global__ __launch_bounds__(256) void pack_mask(const int* __restrict__ mask,
                                                 uint32_t* __restrict__ mb)
{
    int w    = blockIdx.x * 8 + (threadIdx.x >> 5);
    int lane = threadIdx.x & 31;
    int v    = mask[(size_t)w * 32 + lane];
    uint32_t bits = __ballot_sync(0xffffffffu, v != 0);
    if (lane == 0) mb[w] = bits;
}

// ---------------------------------------------------------------------------
// tf32 GEMM core (128x128x32, 256 threads). Two epilogues: fp32 and fp16.
// ---------------------------------------------------------------------------
#define TBM 128
#define TBN 128
#define TBK 32

template <typename OutT>
__global__ __launch_bounds__(256) void gemm_tf32_t(
    const float* __restrict__ A, const float* __restrict__ W,
    const float* __restrict__ bias, OutT* __restrict__ Y, float oscale)
{
    __shared__ uint32_t As[TBM][36];
    __shared__ uint32_t Bs[TBK][136];

    const int tid  = threadIdx.x;
    const int wid  = tid >> 5;
    const int lane = tid & 31;
    const int gid  = lane >> 2;
    const int ctid = lane & 3;
    const int wm   = wid & 3;
    const int wn   = wid >> 2;

    const int bm = blockIdx.y * TBM;
    const int bn = blockIdx.x * TBN;

    float acc[2][8][4];
#pragma unroll
    for (int i = 0; i < 2; i++)
#pragma unroll
        for (int j = 0; j < 8; j++)
#pragma unroll
            for (int t = 0; t < 4; t++) acc[i][j][t] = 0.f;

    for (int k0 = 0; k0 < DMODEL; k0 += TBK) {
#pragma unroll
        for (int i = 0; i < 4; i++) {
            int f  = i * 256 + tid;
            int r  = f >> 3;
            int c4 = (f & 7) * 4;
            float4 v = *(const float4*)(A + (size_t)(bm + r) * DMODEL + k0 + c4);
            As[r][c4 + 0] = f2tf32(v.x); As[r][c4 + 1] = f2tf32(v.y);
            As[r][c4 + 2] = f2tf32(v.z); As[r][c4 + 3] = f2tf32(v.w);
        }
#pragma unroll
        for (int i = 0; i < 4; i++) {
            int f  = i * 256 + tid;
            int r  = f >> 5;
            int c4 = (f & 31) * 4;
            float4 v = *(const float4*)(W + (size_t)(k0 + r) * DMODEL + bn + c4);
            Bs[r][c4 + 0] = f2tf32(v.x); Bs[r][c4 + 1] = f2tf32(v.y);
            Bs[r][c4 + 2] = f2tf32(v.z); Bs[r][c4 + 3] = f2tf32(v.w);
        }
        __syncthreads();

#pragma unroll
        for (int ks = 0; ks < 4; ks++) {
            const int kk = ks * 8;
            uint32_t a[2][4], b[8][2];
#pragma unroll
            for (int mt = 0; mt < 2; mt++) {
                int rb = wm * 32 + mt * 16;
                a[mt][0] = As[rb + gid    ][kk + ctid    ];
                a[mt][1] = As[rb + gid + 8][kk + ctid    ];
                a[mt][2] = As[rb + gid    ][kk + ctid + 4];
                a[mt][3] = As[rb + gid + 8][kk + ctid + 4];
            }
#pragma unroll
            for (int nt = 0; nt < 8; nt++) {
                int nb = wn * 64 + nt * 8;
                b[nt][0] = Bs[kk + ctid    ][nb + gid];
                b[nt][1] = Bs[kk + ctid + 4][nb + gid];
            }
#pragma unroll
            for (int mt = 0; mt < 2; mt++)
#pragma unroll
                for (int nt = 0; nt < 8; nt++)
                    mma_tf32(acc[mt][nt], a[mt], b[nt]);
        }
        __syncthreads();
    }

#pragma unroll
    for (int nt = 0; nt < 8; nt++) {
        int c = bn + wn * 64 + nt * 8 + ctid * 2;
        float b0 = __ldg(bias + c);
        float b1 = __ldg(bias + c + 1);
#pragma unroll
        for (int mt = 0; mt < 2; mt++) {
            int r0 = bm + wm * 32 + mt * 16 + gid;
            float v00 = (acc[mt][nt][0] + b0) * oscale;
            float v01 = (acc[mt][nt][1] + b1) * oscale;
            float v10 = (acc[mt][nt][2] + b0) * oscale;
            float v11 = (acc[mt][nt][3] + b1) * oscale;
            if constexpr (sizeof(OutT) == 4) {
                float2 p0 = make_float2(v00, v01);
                float2 p1 = make_float2(v10, v11);
                *(float2*)((float*)Y + (size_t)r0 * DMODEL + c)       = p0;
                *(float2*)((float*)Y + (size_t)(r0 + 8) * DMODEL + c) = p1;
            } else {
                uint32_t p0 = pack_f16x2(v00, v01);
                uint32_t p1 = pack_f16x2(v10, v11);
                *(uint32_t*)((__half*)Y + (size_t)r0 * DMODEL + c)       = p0;
                *(uint32_t*)((__half*)Y + (size_t)(r0 + 8) * DMODEL + c) = p1;
            }
        }
    }
}

// ---------------------------------------------------------------------------
// Flash attention, fp16 m16n8k16, ldmatrix fragments, bit-packed mask.
// Block: 256 threads = 8 warps; 128 queries/block (16/warp). Key tile 64.
// K,V both [key][d] pitch 72 halfs (144B === 16 mod 128 -> LDSM conflict-free).
// ---------------------------------------------------------------------------
#define FKT 64
#define KVP 72

__global__ __launch_bounds__(256) void flash_f16(
    const __half* __restrict__ Qh, const __half* __restrict__ Kh,
    const __half* __restrict__ Vh, const uint32_t* __restrict__ mbits,
    float* __restrict__ Ctx)
{
    __shared__ __align__(16) __half Ks[FKT * KVP];   // 9 KB
    __shared__ __align__(16) __half Vs[FKT * KVP];   // 9 KB

    const int tid  = threadIdx.x;
    const int w    = tid >> 5;
    const int lane = tid & 31;
    const int gid  = lane >> 2;
    const int ctid = lane & 3;

    const int h  = blockIdx.y;
    const int b  = blockIdx.z;
    const int qb = blockIdx.x * 128 + w * 16;

    // Q fragments held in registers (Q pre-scaled by 1/8)
    uint32_t qa[4][4];
    {
        const __half* q0 = Qh + (size_t)(b * SEQ + qb + gid    ) * DMODEL + h * DK;
        const __half* q1 = Qh + (size_t)(b * SEQ + qb + gid + 8) * DMODEL + h * DK;
#pragma unroll
        for (int t = 0; t < 4; t++) {
            qa[t][0] = *(const uint32_t*)(q0 + 16 * t + 2 * ctid);
            qa[t][1] = *(const uint32_t*)(q1 + 16 * t + 2 * ctid);
            qa[t][2] = *(const uint32_t*)(q0 + 16 * t + 2 * ctid + 8);
            qa[t][3] = *(const uint32_t*)(q1 + 16 * t + 2 * ctid + 8);
        }
    }

    float m0 = -INFINITY, m1 = -INFINITY, l0 = 0.f, l1 = 0.f;
    float o[8][4];
#pragma unroll
    for (int nd = 0; nd < 8; nd++)
#pragma unroll
        for (int t = 0; t < 4; t++) o[nd][t] = 0.f;

    const uint32_t* mb0 = mbits + ((size_t)(b * SEQ) + qb + gid) * MW;
    const uint32_t* mb1 = mb0 + 8 * MW;

    // Precomputed LDSM base addresses (lane-dependent, loop-invariant)
    const uint32_t ks_base = sptr(&Ks[(lane & 7) * KVP + (lane >> 3) * 8]);
    const uint32_t vs_base = sptr(&Vs[((lane & 7) + (lane >> 3) * 8) * KVP]);

    for (int kt = 0; kt < SEQ; kt += FKT) {
        __syncthreads();
        // K,V tiles: 64x64 halfs = 512 uint4 each; 2 per thread each
#pragma unroll
        for (int i = 0; i < 2; i++) {
            int f  = i * 256 + tid;
            int r  = f >> 3;
            int c8 = (f & 7) * 8;
            size_t ga = (size_t)(b * SEQ + kt + r) * DMODEL + h * DK + c8;
            *(uint4*)(&Ks[r * KVP + c8]) = *(const uint4*)(Kh + ga);
            *(uint4*)(&Vs[r * KVP + c8]) = *(const uint4*)(Vh + ga);
        }
        __syncthreads();

        // mask bits for this tile (2 words per row)
        uint2 w0 = *(const uint2*)(mb0 + (kt >> 5));
        uint2 w1 = *(const uint2*)(mb1 + (kt >> 5));

        // ---- S = Q K^T ----
        float sc[8][4];
#pragma unroll
        for (int nt = 0; nt < 8; nt++) {
#pragma unroll
            for (int t4 = 0; t4 < 4; t4++) sc[nt][t4] = 0.f;
            uint32_t bk[8];
            uint32_t base = ks_base + nt * 8 * KVP * 2;   // +8 key rows
            ldsm_x4(bk,     base);                        // k 0..31
            ldsm_x4(bk + 4, base + 64);                   // k 32..63 (+32 halfs)
            mma_f16(sc[nt], qa[0], bk);
            mma_f16(sc[nt], qa[1], bk + 2);
            mma_f16(sc[nt], qa[2], bk + 4);
            mma_f16(sc[nt], qa[3], bk + 6);
        }

        // ---- mask from bits ----
#pragma unroll
        for (int nt = 0; nt < 8; nt++) {
            int kl = nt * 8 + 2 * ctid;          // 0..62
            uint32_t wr0 = (kl & 32) ? w0.y : w0.x;
            uint32_t wr1 = (kl & 32) ? w1.y : w1.x;
            int sh = kl & 31;
            if ((wr0 >> sh) & 1)       sc[nt][0] = NEGV;
            if ((wr0 >> (sh + 1)) & 1) sc[nt][1] = NEGV;
            if ((wr1 >> sh) & 1)       sc[nt][2] = NEGV;
            if ((wr1 >> (sh + 1)) & 1) sc[nt][3] = NEGV;
        }

        // ---- online softmax ----
        float t0 = sc[0][0], t1 = sc[0][2];
#pragma unroll
        for (int nt = 0; nt < 8; nt++) {
            t0 = fmaxf(t0, fmaxf(sc[nt][0], sc[nt][1]));
            t1 = fmaxf(t1, fmaxf(sc[nt][2], sc[nt][3]));
        }
        t0 = fmaxf(t0, __shfl_xor_sync(0xffffffffu, t0, 1));
        t0 = fmaxf(t0, __shfl_xor_sync(0xffffffffu, t0, 2));
        t1 = fmaxf(t1, __shfl_xor_sync(0xffffffffu, t1, 1));
        t1 = fmaxf(t1, __shfl_xor_sync(0xffffffffu, t1, 2));
        float nm0 = fmaxf(m0, t0), nm1 = fmaxf(m1, t1);
        float al0 = __expf(m0 - nm0), al1 = __expf(m1 - nm1);
        m0 = nm0; m1 = nm1;

        uint32_t pa[4][4];
        float ps0 = 0.f, ps1 = 0.f;
#pragma unroll
        for (int nt = 0; nt < 8; nt++) {
            float p00 = __expf(sc[nt][0] - nm0);
            float p01 = __expf(sc[nt][1] - nm0);
            float p10 = __expf(sc[nt][2] - nm1);
            float p11 = __expf(sc[nt][3] - nm1);
            ps0 += p00 + p01;
            ps1 += p10 + p11;
            int tt = nt >> 1;
            int hi = (nt & 1) ? 2 : 0;
            pa[tt][hi + 0] = pack_f16x2(p00, p01);
            pa[tt][hi + 1] = pack_f16x2(p10, p11);
        }
        ps0 += __shfl_xor_sync(0xffffffffu, ps0, 1);
        ps0 += __shfl_xor_sync(0xffffffffu, ps0, 2);
        ps1 += __shfl_xor_sync(0xffffffffu, ps1, 1);
        ps1 += __shfl_xor_sync(0xffffffffu, ps1, 2);
        l0 = l0 * al0 + ps0;
        l1 = l1 * al1 + ps1;

        // ---- O = O*alpha + P V ----
#pragma unroll
        for (int nd = 0; nd < 8; nd++) {
            o[nd][0] *= al0; o[nd][1] *= al0;
            o[nd][2] *= al1; o[nd][3] *= al1;
        }
#pragma unroll
        for (int nd = 0; nd < 8; nd++) {
            uint32_t bv[8];
            uint32_t base = vs_base + nd * 16;            // +8 d cols (16 B)
            ldsm_x4_t(bv,     base);                      // keys 0..31
            ldsm_x4_t(bv + 4, base + 32 * KVP * 2);       // keys 32..63
            mma_f16(o[nd], pa[0], bv);
            mma_f16(o[nd], pa[1], bv + 2);
            mma_f16(o[nd], pa[2], bv + 4);
            mma_f16(o[nd], pa[3], bv + 6);
        }
    }

    // ---- normalize + store ----
    float i0 = 1.f / l0, i1 = 1.f / l1;
    size_t r0 = (size_t)(b * SEQ + qb + gid);
#pragma unroll
    for (int nd = 0; nd < 8; nd++) {
        int c = h * DK + nd * 8 + 2 * ctid;
        float2 v0, v1;
        v0.x = o[nd][0] * i0; v0.y = o[nd][1] * i0;
        v1.x = o[nd][2] * i1; v1.y = o[nd][3] * i1;
        *(float2*)(Ctx + r0 * DMODEL + c)       = v0;
        *(float2*)(Ctx + (r0 + 8) * DMODEL + c) = v1;
    }
}

// ---------------------------------------------------------------------------
// Launch
// ---------------------------------------------------------------------------
extern "C" void kernel_launch(void* const* d_in, const int* in_sizes, int n_in,
                              void* d_out, int out_size)
{
    const float* x    = (const float*)d_in[0];
    const int*   mask = (const int*)d_in[1];
    const float* Wq   = (const float*)d_in[2];
    const float* bq   = (const float*)d_in[3];
    const float* Wk   = (const float*)d_in[4];
    const float* bk   = (const float*)d_in[5];
    const float* Wv   = (const float*)d_in[6];
    const float* bv   = (const float*)d_in[7];
    const float* Wo   = (const float*)d_in[8];
    const float* bo   = (const float*)d_in[9];
    float* out = (float*)d_out;

    __half *Qh, *Kh, *Vh; float* Cb; uint32_t* Mb;
    cudaGetSymbolAddress((void**)&Qh, g_Qh);
    cudaGetSymbolAddress((void**)&Kh, g_Kh);
    cudaGetSymbolAddress((void**)&Vh, g_Vh);
    cudaGetSymbolAddress((void**)&Cb, g_C);
    cudaGetSymbolAddress((void**)&Mb, g_Mb);

    pack_mask<<<BATCH * SEQ * MW / 8, 256>>>(mask, Mb);

    dim3 gg(DMODEL / TBN, MTOT / TBM);   // (8, 64)
    gemm_tf32_t<__half><<<gg, 256>>>(x, Wq, bq, Qh, 0.125f);  // Q pre-scaled
    gemm_tf32_t<__half><<<gg, 256>>>(x, Wk, bk, Kh, 1.0f);
    gemm_tf32_t<__half><<<gg, 256>>>(x, Wv, bv, Vh, 1.0f);

    dim3 fg(SEQ / 128, NHEADS, BATCH);   // (16, 16, 4)
    flash_f16<<<fg, 256>>>(Qh, Kh, Vh, Mb, Cb);

    gemm_tf32_t<float><<<gg, 256>>>(Cb, Wo, bo, out, 1.0f);
}

// round 9
// speedup vs baseline: 5.1369x; 1.1506x over previous
#include <cuda_runtime.h>
#include <cuda_fp16.h>
#include <cstdint>
#include <math.h>

#define BATCH 4
#define SEQ   2048
#define DMODEL 1024
#define NHEADS 16
#define DK    64
#define MTOT  (BATCH*SEQ)      // 8192
#define NEGV  (-1e9f)
#define MW    (SEQ/32)         // 64 mask words per row

// Scratch (alloc-free rule: __device__ globals).
__device__ __half   g_Xh[MTOT * DMODEL];     // x in fp16
__device__ __half   g_Wh[4 * DMODEL * DMODEL]; // Wq,Wk,Wv,Wo in fp16
__device__ __half   g_Qh[MTOT * DMODEL];     // pre-scaled by 0.125
__device__ __half   g_Kh[MTOT * DMODEL];
__device__ __half   g_Vh[MTOT * DMODEL];
__device__ __half   g_Ch[MTOT * DMODEL];     // ctx in fp16
__device__ uint32_t g_Mb[BATCH * SEQ * MW];  // bit-packed mask (2 MB)

__device__ __forceinline__ uint32_t pack_f16x2(float lo, float hi) {
    uint32_t r;
    asm("cvt.rn.f16x2.f32 %0, %1, %2;" : "=r"(r) : "f"(hi), "f"(lo));
    return r;
}

__device__ __forceinline__ uint32_t sptr(const void* p) {
    return (uint32_t)__cvta_generic_to_shared(p);
}

__device__ __forceinline__ void ldsm_x4(uint32_t* r, uint32_t addr) {
    asm volatile("ldmatrix.sync.aligned.m8n8.x4.shared.b16 {%0,%1,%2,%3}, [%4];"
                 : "=r"(r[0]), "=r"(r[1]), "=r"(r[2]), "=r"(r[3]) : "r"(addr));
}

__device__ __forceinline__ void ldsm_x4_t(uint32_t* r, uint32_t addr) {
    asm volatile("ldmatrix.sync.aligned.m8n8.x4.trans.shared.b16 {%0,%1,%2,%3}, [%4];"
                 : "=r"(r[0]), "=r"(r[1]), "=r"(r[2]), "=r"(r[3]) : "r"(addr));
}

__device__ __forceinline__ void mma_f16(float* c, const uint32_t* a, const uint32_t* b) {
    asm volatile(
        "mma.sync.aligned.m16n8k16.row.col.f32.f16.f16.f32 "
        "{%0,%1,%2,%3}, {%4,%5,%6,%7}, {%8,%9}, {%0,%1,%2,%3};"
        : "+f"(c[0]), "+f"(c[1]), "+f"(c[2]), "+f"(c[3])
        : "r"(a[0]), "r"(a[1]), "r"(a[2]), "r"(a[3]), "r"(b[0]), "r"(b[1]));
}

// ---------------------------------------------------------------------------
// fp32 -> fp16 bulk convert (vectorized: 4 elts/thread)
// ---------------------------------------------------------------------------
__global__ __launch_bounds__(256) void cvt_f16(const float* __restrict__ src,
                                               __half* __restrict__ dst, int n4)
{
    int i = blockIdx.x * 256 + threadIdx.x;
    if (i >= n4) return;
    float4 v = *(const float4*)(src + (size_t)i * 4);
    uint2 o;
    o.x = pack_f16x2(v.x, v.y);
    o.y = pack_f16x2(v.z, v.w);
    *(uint2*)(dst + (size_t)i * 4) = o;
}

// ---------------------------------------------------------------------------
// Bit-pack the int32 mask: one warp -> one uint32 word (32 keys).
// ---------------------------------------------------------------------------
__global__ __launch_bounds__(256) void pack_mask(const int* __restrict__ mask,
                                                 uint32_t* __restrict__ mb)
{
    int w    = blockIdx.x * 8 + (threadIdx.x >> 5);
    int lane = threadIdx.x & 31;
    int v    = mask[(size_t)w * 32 + lane];
    uint32_t bits = __ballot_sync(0xffffffffu, v != 0);
    if (lane == 0) mb[w] = bits;
}

// ---------------------------------------------------------------------------
// fp16 GEMM: Y[M,D] = A[M,D] @ W[D,D] + bias. A,W fp16; acc fp32.
// Block 128x128, K-tile 64, 256 threads (8 warps: 4M x 2N).
// ldmatrix for all fragments. Pitches 72/136 halfs (==16 mod 128 bytes).
// ---------------------------------------------------------------------------
#define TBM 128
#define TBN 128
#define TBK 64
#define AP  72
#define BP  136

template <typename OutT>
__global__ __launch_bounds__(256) void gemm_f16_t(
    const __half* __restrict__ A, const __half* __restrict__ W,
    const float* __restrict__ bias, OutT* __restrict__ Y, float oscale)
{
    __shared__ __align__(16) __half As[TBM * AP];   // 18.4 KB
    __shared__ __align__(16) __half Bs[TBK * BP];   // 17.4 KB

    const int tid  = threadIdx.x;
    const int wid  = tid >> 5;
    const int lane = tid & 31;
    const int gid  = lane >> 2;
    const int ctid = lane & 3;
    const int wm   = wid & 3;
    const int wn   = wid >> 2;

    const int bm = blockIdx.y * TBM;
    const int bn = blockIdx.x * TBN;

    float acc[2][8][4];
#pragma unroll
    for (int i = 0; i < 2; i++)
#pragma unroll
        for (int j = 0; j < 8; j++)
#pragma unroll
            for (int t = 0; t < 4; t++) acc[i][j][t] = 0.f;

    // ldmatrix base addresses (lane-dependent, loop-invariant)
    const uint32_t a_base = sptr(&As[(wm * 32 + (lane & 15)) * AP + (lane >> 4) * 8]);
    const uint32_t b_base = sptr(&Bs[((lane & 7) + (lane >> 3) * 8) * BP + wn * 64]);

    for (int k0 = 0; k0 < DMODEL; k0 += TBK) {
        // A tile: 128x64 halfs = 1024 uint4; 4 per thread
#pragma unroll
        for (int i = 0; i < 4; i++) {
            int f  = i * 256 + tid;          // 0..1023
            int r  = f >> 3;                 // 0..127
            int c8 = (f & 7) * 8;            // 0..56
            *(uint4*)(&As[r * AP + c8]) =
                *(const uint4*)(A + (size_t)(bm + r) * DMODEL + k0 + c8);
        }
        // W tile: 64x128 halfs = 1024 uint4; 4 per thread
#pragma unroll
        for (int i = 0; i < 4; i++) {
            int f  = i * 256 + tid;
            int r  = f >> 4;                 // 0..63
            int c8 = (f & 15) * 8;           // 0..120
            *(uint4*)(&Bs[r * BP + c8]) =
                *(const uint4*)(W + (size_t)(k0 + r) * DMODEL + bn + c8);
        }
        __syncthreads();

#pragma unroll
        for (int kh = 0; kh < 2; kh++) {                 // k halves 0-31, 32-63
            uint32_t a[2][2][4];
#pragma unroll
            for (int mt = 0; mt < 2; mt++)
#pragma unroll
                for (int ks = 0; ks < 2; ks++)
                    ldsm_x4(a[mt][ks], a_base + mt * 16 * AP * 2 + (kh * 2 + ks) * 32);
#pragma unroll
            for (int nt = 0; nt < 8; nt++) {
                uint32_t bb[4];
                ldsm_x4_t(bb, b_base + kh * 32 * BP * 2 + nt * 16);
                mma_f16(acc[0][nt], a[0][0], bb);
                mma_f16(acc[0][nt], a[0][1], bb + 2);
                mma_f16(acc[1][nt], a[1][0], bb);
                mma_f16(acc[1][nt], a[1][1], bb + 2);
            }
        }
        __syncthreads();
    }

#pragma unroll
    for (int nt = 0; nt < 8; nt++) {
        int c = bn + wn * 64 + nt * 8 + ctid * 2;
        float b0 = __ldg(bias + c);
        float b1 = __ldg(bias + c + 1);
#pragma unroll
        for (int mt = 0; mt < 2; mt++) {
            int r0 = bm + wm * 32 + mt * 16 + gid;
            float v00 = (acc[mt][nt][0] + b0) * oscale;
            float v01 = (acc[mt][nt][1] + b1) * oscale;
            float v10 = (acc[mt][nt][2] + b0) * oscale;
            float v11 = (acc[mt][nt][3] + b1) * oscale;
            if constexpr (sizeof(OutT) == 4) {
                float2 p0 = make_float2(v00, v01);
                float2 p1 = make_float2(v10, v11);
                *(float2*)((float*)Y + (size_t)r0 * DMODEL + c)       = p0;
                *(float2*)((float*)Y + (size_t)(r0 + 8) * DMODEL + c) = p1;
            } else {
                uint32_t p0 = pack_f16x2(v00, v01);
                uint32_t p1 = pack_f16x2(v10, v11);
                *(uint32_t*)((__half*)Y + (size_t)r0 * DMODEL + c)       = p0;
                *(uint32_t*)((__half*)Y + (size_t)(r0 + 8) * DMODEL + c) = p1;
            }
        }
    }
}

// ---------------------------------------------------------------------------
// Flash attention, fp16 m16n8k16, ldmatrix fragments, bit-packed mask.
// Block: 256 threads = 8 warps; 128 queries/block (16/warp). Key tile 64.
// Writes ctx as fp16.
// ---------------------------------------------------------------------------
#define FKT 64
#define KVP 72

__global__ __launch_bounds__(256) void flash_f16(
    const __half* __restrict__ Qh, const __half* __restrict__ Kh,
    const __half* __restrict__ Vh, const uint32_t* __restrict__ mbits,
    __half* __restrict__ Ctx)
{
    __shared__ __align__(16) __half Ks[FKT * KVP];   // 9 KB
    __shared__ __align__(16) __half Vs[FKT * KVP];   // 9 KB

    const int tid  = threadIdx.x;
    const int w    = tid >> 5;
    const int lane = tid & 31;
    const int gid  = lane >> 2;
    const int ctid = lane & 3;

    const int h  = blockIdx.y;
    const int b  = blockIdx.z;
    const int qb = blockIdx.x * 128 + w * 16;

    // Q fragments held in registers (Q pre-scaled by 1/8)
    uint32_t qa[4][4];
    {
        const __half* q0 = Qh + (size_t)(b * SEQ + qb + gid    ) * DMODEL + h * DK;
        const __half* q1 = Qh + (size_t)(b * SEQ + qb + gid + 8) * DMODEL + h * DK;
#pragma unroll
        for (int t = 0; t < 4; t++) {
            qa[t][0] = *(const uint32_t*)(q0 + 16 * t + 2 * ctid);
            qa[t][1] = *(const uint32_t*)(q1 + 16 * t + 2 * ctid);
            qa[t][2] = *(const uint32_t*)(q0 + 16 * t + 2 * ctid + 8);
            qa[t][3] = *(const uint32_t*)(q1 + 16 * t + 2 * ctid + 8);
        }
    }

    float m0 = -INFINITY, m1 = -INFINITY, l0 = 0.f, l1 = 0.f;
    float o[8][4];
#pragma unroll
    for (int nd = 0; nd < 8; nd++)
#pragma unroll
        for (int t = 0; t < 4; t++) o[nd][t] = 0.f;

    const uint32_t* mb0 = mbits + ((size_t)(b * SEQ) + qb + gid) * MW;
    const uint32_t* mb1 = mb0 + 8 * MW;

    const uint32_t ks_base = sptr(&Ks[(lane & 7) * KVP + (lane >> 3) * 8]);
    const uint32_t vs_base = sptr(&Vs[((lane & 7) + (lane >> 3) * 8) * KVP]);

    for (int kt = 0; kt < SEQ; kt += FKT) {
        __syncthreads();
#pragma unroll
        for (int i = 0; i < 2; i++) {
            int f  = i * 256 + tid;
            int r  = f >> 3;
            int c8 = (f & 7) * 8;
            size_t ga = (size_t)(b * SEQ + kt + r) * DMODEL + h * DK + c8;
            *(uint4*)(&Ks[r * KVP + c8]) = *(const uint4*)(Kh + ga);
            *(uint4*)(&Vs[r * KVP + c8]) = *(const uint4*)(Vh + ga);
        }
        __syncthreads();

        uint2 w0 = *(const uint2*)(mb0 + (kt >> 5));
        uint2 w1 = *(const uint2*)(mb1 + (kt >> 5));

        // ---- S = Q K^T ----
        float sc[8][4];
#pragma unroll
        for (int nt = 0; nt < 8; nt++) {
#pragma unroll
            for (int t4 = 0; t4 < 4; t4++) sc[nt][t4] = 0.f;
            uint32_t bk[8];
            uint32_t base = ks_base + nt * 8 * KVP * 2;
            ldsm_x4(bk,     base);
            ldsm_x4(bk + 4, base + 64);
            mma_f16(sc[nt], qa[0], bk);
            mma_f16(sc[nt], qa[1], bk + 2);
            mma_f16(sc[nt], qa[2], bk + 4);
            mma_f16(sc[nt], qa[3], bk + 6);
        }

        // ---- mask from bits ----
#pragma unroll
        for (int nt = 0; nt < 8; nt++) {
            int kl = nt * 8 + 2 * ctid;
            uint32_t wr0 = (kl & 32) ? w0.y : w0.x;
            uint32_t wr1 = (kl & 32) ? w1.y : w1.x;
            int sh = kl & 31;
            if ((wr0 >> sh) & 1)       sc[nt][0] = NEGV;
            if ((wr0 >> (sh + 1)) & 1) sc[nt][1] = NEGV;
            if ((wr1 >> sh) & 1)       sc[nt][2] = NEGV;
            if ((wr1 >> (sh + 1)) & 1) sc[nt][3] = NEGV;
        }

        // ---- online softmax ----
        float t0 = sc[0][0], t1 = sc[0][2];
#pragma unroll
        for (int nt = 0; nt < 8; nt++) {
            t0 = fmaxf(t0, fmaxf(sc[nt][0], sc[nt][1]));
            t1 = fmaxf(t1, fmaxf(sc[nt][2], sc[nt][3]));
        }
        t0 = fmaxf(t0, __shfl_xor_sync(0xffffffffu, t0, 1));
        t0 = fmaxf(t0, __shfl_xor_sync(0xffffffffu, t0, 2));
        t1 = fmaxf(t1, __shfl_xor_sync(0xffffffffu, t1, 1));
        t1 = fmaxf(t1, __shfl_xor_sync(0xffffffffu, t1, 2));
        float nm0 = fmaxf(m0, t0), nm1 = fmaxf(m1, t1);
        float al0 = __expf(m0 - nm0), al1 = __expf(m1 - nm1);
        m0 = nm0; m1 = nm1;

        uint32_t pa[4][4];
        float ps0 = 0.f, ps1 = 0.f;
#pragma unroll
        for (int nt = 0; nt < 8; nt++) {
            float p00 = __expf(sc[nt][0] - nm0);
            float p01 = __expf(sc[nt][1] - nm0);
            float p10 = __expf(sc[nt][2] - nm1);
            float p11 = __expf(sc[nt][3] - nm1);
            ps0 += p00 + p01;
            ps1 += p10 + p11;
            int tt = nt >> 1;
            int hi = (nt & 1) ? 2 : 0;
            pa[tt][hi + 0] = pack_f16x2(p00, p01);
            pa[tt][hi + 1] = pack_f16x2(p10, p11);
        }
        ps0 += __shfl_xor_sync(0xffffffffu, ps0, 1);
        ps0 += __shfl_xor_sync(0xffffffffu, ps0, 2);
        ps1 += __shfl_xor_sync(0xffffffffu, ps1, 1);
        ps1 += __shfl_xor_sync(0xffffffffu, ps1, 2);
        l0 = l0 * al0 + ps0;
        l1 = l1 * al1 + ps1;

        // ---- O = O*alpha + P V ----
#pragma unroll
        for (int nd = 0; nd < 8; nd++) {
            o[nd][0] *= al0; o[nd][1] *= al0;
            o[nd][2] *= al1; o[nd][3] *= al1;
        }
#pragma unroll
        for (int nd = 0; nd < 8; nd++) {
            uint32_t bv[8];
            uint32_t base = vs_base + nd * 16;
            ldsm_x4_t(bv,     base);
            ldsm_x4_t(bv + 4, base + 32 * KVP * 2);
            mma_f16(o[nd], pa[0], bv);
            mma_f16(o[nd], pa[1], bv + 2);
            mma_f16(o[nd], pa[2], bv + 4);
            mma_f16(o[nd], pa[3], bv + 6);
        }
    }

    // ---- normalize + store (fp16 ctx) ----
    float i0 = 1.f / l0, i1 = 1.f / l1;
    size_t r0 = (size_t)(b * SEQ + qb + gid);
#pragma unroll
    for (int nd = 0; nd < 8; nd++) {
        int c = h * DK + nd * 8 + 2 * ctid;
        uint32_t p0 = pack_f16x2(o[nd][0] * i0, o[nd][1] * i0);
        uint32_t p1 = pack_f16x2(o[nd][2] * i1, o[nd][3] * i1);
        *(uint32_t*)(Ctx + r0 * DMODEL + c)       = p0;
        *(uint32_t*)(Ctx + (r0 + 8) * DMODEL + c) = p1;
    }
}

// ---------------------------------------------------------------------------
// Launch
// ---------------------------------------------------------------------------
extern "C" void kernel_launch(void* const* d_in, const int* in_sizes, int n_in,
                              void* d_out, int out_size)
{
    const float* x    = (const float*)d_in[0];
    const int*   mask = (const int*)d_in[1];
    const float* Wq   = (const float*)d_in[2];
    const float* bq   = (const float*)d_in[3];
    const float* Wk   = (const float*)d_in[4];
    const float* bk   = (const float*)d_in[5];
    const float* Wv   = (const float*)d_in[6];
    const float* bv   = (const float*)d_in[7];
    const float* Wo   = (const float*)d_in[8];
    const float* bo   = (const float*)d_in[9];
    float* out = (float*)d_out;

    __half *Xh, *Wh, *Qh, *Kh, *Vh, *Ch; uint32_t* Mb;
    cudaGetSymbolAddress((void**)&Xh, g_Xh);
    cudaGetSymbolAddress((void**)&Wh, g_Wh);
    cudaGetSymbolAddress((void**)&Qh, g_Qh);
    cudaGetSymbolAddress((void**)&Kh, g_Kh);
    cudaGetSymbolAddress((void**)&Vh, g_Vh);
    cudaGetSymbolAddress((void**)&Ch, g_Ch);
    cudaGetSymbolAddress((void**)&Mb, g_Mb);

    pack_mask<<<BATCH * SEQ * MW / 8, 256>>>(mask, Mb);

    const int NX = MTOT * DMODEL / 4;     // x: 8M elts -> 2M float4
    const int NW = DMODEL * DMODEL / 4;   // W: 1M elts -> 256K float4
    cvt_f16<<<NX / 256, 256>>>(x,  Xh, NX);
    cvt_f16<<<NW / 256, 256>>>(Wq, Wh + 0 * DMODEL * DMODEL, NW);
    cvt_f16<<<NW / 256, 256>>>(Wk, Wh + 1 * DMODEL * DMODEL, NW);
    cvt_f16<<<NW / 256, 256>>>(Wv, Wh + 2 * DMODEL * DMODEL, NW);
    cvt_f16<<<NW / 256, 256>>>(Wo, Wh + 3 * DMODEL * DMODEL, NW);

    dim3 gg(DMODEL / TBN, MTOT / TBM);   // (8, 64)
    gemm_f16_t<__half><<<gg, 256>>>(Xh, Wh + 0 * DMODEL * DMODEL, bq, Qh, 0.125f);
    gemm_f16_t<__half><<<gg, 256>>>(Xh, Wh + 1 * DMODEL * DMODEL, bk, Kh, 1.0f);
    gemm_f16_t<__half><<<gg, 256>>>(Xh, Wh + 2 * DMODEL * DMODEL, bv, Vh, 1.0f);

    dim3 fg(SEQ / 128, NHEADS, BATCH);   // (16, 16, 4)
    flash_f16<<<fg, 256>>>(Qh, Kh, Vh, Mb, Ch);

    gemm_f16_t<float><<<gg, 256>>>(Ch, Wh + 3 * DMODEL * DMODEL, bo, out, 1.0f);
}

// round 10
// speedup vs baseline: 7.1518x; 1.3922x over previous
#include <cuda_runtime.h>
#include <cuda_fp16.h>
#include <cstdint>
#include <math.h>

#define BATCH 4
#define SEQ   2048
#define DMODEL 1024
#define NHEADS 16
#define DK    64
#define MTOT  (BATCH*SEQ)      // 8192
#define NEGV  (-1e9f)
#define MW    (SEQ/32)         // 64 mask words per row

// Scratch (alloc-free rule: __device__ globals).
__device__ __half   g_Xh[MTOT * DMODEL];       // x in fp16
__device__ __half   g_Wh[4 * DMODEL * DMODEL]; // Wq,Wk,Wv,Wo in fp16
__device__ __half   g_Qh[MTOT * DMODEL];       // pre-scaled by 0.125
__device__ __half   g_Kh[MTOT * DMODEL];
__device__ __half   g_Vh[MTOT * DMODEL];
__device__ __half   g_Ch[MTOT * DMODEL];       // ctx in fp16
__device__ uint32_t g_Mb[BATCH * SEQ * MW];    // bit-packed mask (2 MB)

__device__ __forceinline__ uint32_t pack_f16x2(float lo, float hi) {
    uint32_t r;
    asm("cvt.rn.f16x2.f32 %0, %1, %2;" : "=r"(r) : "f"(hi), "f"(lo));
    return r;
}

__device__ __forceinline__ uint32_t sptr(const void* p) {
    return (uint32_t)__cvta_generic_to_shared(p);
}

__device__ __forceinline__ void cp_async16(uint32_t smem, const void* g) {
    asm volatile("cp.async.cg.shared.global [%0], [%1], 16;" :: "r"(smem), "l"(g));
}
#define CP_COMMIT() asm volatile("cp.async.commit_group;")
#define CP_WAIT(N)  asm volatile("cp.async.wait_group %0;" :: "n"(N))

__device__ __forceinline__ void ldsm_x4(uint32_t* r, uint32_t addr) {
    asm volatile("ldmatrix.sync.aligned.m8n8.x4.shared.b16 {%0,%1,%2,%3}, [%4];"
                 : "=r"(r[0]), "=r"(r[1]), "=r"(r[2]), "=r"(r[3]) : "r"(addr));
}

__device__ __forceinline__ void ldsm_x4_t(uint32_t* r, uint32_t addr) {
    asm volatile("ldmatrix.sync.aligned.m8n8.x4.trans.shared.b16 {%0,%1,%2,%3}, [%4];"
                 : "=r"(r[0]), "=r"(r[1]), "=r"(r[2]), "=r"(r[3]) : "r"(addr));
}

__device__ __forceinline__ void mma_f16(float* c, const uint32_t* a, const uint32_t* b) {
    asm volatile(
        "mma.sync.aligned.m16n8k16.row.col.f32.f16.f16.f32 "
        "{%0,%1,%2,%3}, {%4,%5,%6,%7}, {%8,%9}, {%0,%1,%2,%3};"
        : "+f"(c[0]), "+f"(c[1]), "+f"(c[2]), "+f"(c[3])
        : "r"(a[0]), "r"(a[1]), "r"(a[2]), "r"(a[3]), "r"(b[0]), "r"(b[1]));
}

// ---------------------------------------------------------------------------
// fp32 -> fp16 bulk convert
// ---------------------------------------------------------------------------
__global__ __launch_bounds__(256) void cvt_f16(const float* __restrict__ src,
                                               __half* __restrict__ dst, int n4)
{
    int i = blockIdx.x * 256 + threadIdx.x;
    if (i >= n4) return;
    float4 v = *(const float4*)(src + (size_t)i * 4);
    uint2 o;
    o.x = pack_f16x2(v.x, v.y);
    o.y = pack_f16x2(v.z, v.w);
    *(uint2*)(dst + (size_t)i * 4) = o;
}

// ---------------------------------------------------------------------------
// Bit-pack the int32 mask
// ---------------------------------------------------------------------------
__global__ __launch_bounds__(256) void pack_mask(const int* __restrict__ mask,
                                                 uint32_t* __restrict__ mb)
{
    int w    = blockIdx.x * 8 + (threadIdx.x >> 5);
    int lane = threadIdx.x & 31;
    int v    = mask[(size_t)w * 32 + lane];
    uint32_t bits = __ballot_sync(0xffffffffu, v != 0);
    if (lane == 0) mb[w] = bits;
}

// ---------------------------------------------------------------------------
// fp16 GEMM with cp.async 2-stage pipeline.
// Block 128x128, K-tile 64, 256 threads (8 warps: 4M x 2N).
// ---------------------------------------------------------------------------
#define TBM 128
#define TBN 128
#define TBK 64
#define AP  72
#define BP  136
#define NKT (DMODEL / TBK)   // 16

template <typename OutT>
__global__ __launch_bounds__(256) void gemm_f16_t(
    const __half* __restrict__ A, const __half* __restrict__ W,
    const float* __restrict__ bias, OutT* __restrict__ Y, float oscale)
{
    __shared__ __align__(16) __half As[2][TBM * AP];   // 2 x 18.4 KB
    __shared__ __align__(16) __half Bs[2][TBK * BP];   // 2 x 17.4 KB

    const int tid  = threadIdx.x;
    const int wid  = tid >> 5;
    const int lane = tid & 31;
    const int gid  = lane >> 2;
    const int ctid = lane & 3;
    const int wm   = wid & 3;
    const int wn   = wid >> 2;

    const int bm = blockIdx.y * TBM;
    const int bn = blockIdx.x * TBN;

    float acc[2][8][4];
#pragma unroll
    for (int i = 0; i < 2; i++)
#pragma unroll
        for (int j = 0; j < 8; j++)
#pragma unroll
            for (int t = 0; t < 4; t++) acc[i][j][t] = 0.f;

    // Per-thread load coordinates (A: 4 x uint4, B: 4 x uint4)
    int ar[4], ac[4], br[4], bc[4];
#pragma unroll
    for (int i = 0; i < 4; i++) {
        int f = i * 256 + tid;
        ar[i] = f >> 3;  ac[i] = (f & 7) * 8;
        br[i] = f >> 4;  bc[i] = (f & 15) * 8;
    }

    // ldmatrix bases per stage
    uint32_t a_base[2], b_base[2];
#pragma unroll
    for (int st = 0; st < 2; st++) {
        a_base[st] = sptr(&As[st][(wm * 32 + (lane & 15)) * AP + (lane >> 4) * 8]);
        b_base[st] = sptr(&Bs[st][((lane & 7) + (lane >> 3) * 8) * BP + wn * 64]);
    }

    // prefetch stage 0
#pragma unroll
    for (int i = 0; i < 4; i++) {
        cp_async16(sptr(&As[0][ar[i] * AP + ac[i]]),
                   A + (size_t)(bm + ar[i]) * DMODEL + ac[i]);
        cp_async16(sptr(&Bs[0][br[i] * BP + bc[i]]),
                   W + (size_t)br[i] * DMODEL + bn + bc[i]);
    }
    CP_COMMIT();

    for (int kt = 0; kt < NKT; kt++) {
        const int cur = kt & 1;
        if (kt + 1 < NKT) {
            const int nxt = (kt + 1) & 1;
            const int k0  = (kt + 1) * TBK;
#pragma unroll
            for (int i = 0; i < 4; i++) {
                cp_async16(sptr(&As[nxt][ar[i] * AP + ac[i]]),
                           A + (size_t)(bm + ar[i]) * DMODEL + k0 + ac[i]);
                cp_async16(sptr(&Bs[nxt][br[i] * BP + bc[i]]),
                           W + (size_t)(k0 + br[i]) * DMODEL + bn + bc[i]);
            }
            CP_COMMIT();
            CP_WAIT(1);
        } else {
            CP_WAIT(0);
        }
        __syncthreads();

#pragma unroll
        for (int kh = 0; kh < 2; kh++) {
            uint32_t a[2][2][4];
#pragma unroll
            for (int mt = 0; mt < 2; mt++)
#pragma unroll
                for (int ks = 0; ks < 2; ks++)
                    ldsm_x4(a[mt][ks], a_base[cur] + mt * 16 * AP * 2 + (kh * 2 + ks) * 32);
#pragma unroll
            for (int nt = 0; nt < 8; nt++) {
                uint32_t bb[4];
                ldsm_x4_t(bb, b_base[cur] + kh * 32 * BP * 2 + nt * 16);
                mma_f16(acc[0][nt], a[0][0], bb);
                mma_f16(acc[0][nt], a[0][1], bb + 2);
                mma_f16(acc[1][nt], a[1][0], bb);
                mma_f16(acc[1][nt], a[1][1], bb + 2);
            }
        }
        __syncthreads();
    }

#pragma unroll
    for (int nt = 0; nt < 8; nt++) {
        int c = bn + wn * 64 + nt * 8 + ctid * 2;
        float b0 = __ldg(bias + c);
        float b1 = __ldg(bias + c + 1);
#pragma unroll
        for (int mt = 0; mt < 2; mt++) {
            int r0 = bm + wm * 32 + mt * 16 + gid;
            float v00 = (acc[mt][nt][0] + b0) * oscale;
            float v01 = (acc[mt][nt][1] + b1) * oscale;
            float v10 = (acc[mt][nt][2] + b0) * oscale;
            float v11 = (acc[mt][nt][3] + b1) * oscale;
            if constexpr (sizeof(OutT) == 4) {
                float2 p0 = make_float2(v00, v01);
                float2 p1 = make_float2(v10, v11);
                *(float2*)((float*)Y + (size_t)r0 * DMODEL + c)       = p0;
                *(float2*)((float*)Y + (size_t)(r0 + 8) * DMODEL + c) = p1;
            } else {
                uint32_t p0 = pack_f16x2(v00, v01);
                uint32_t p1 = pack_f16x2(v10, v11);
                *(uint32_t*)((__half*)Y + (size_t)r0 * DMODEL + c)       = p0;
                *(uint32_t*)((__half*)Y + (size_t)(r0 + 8) * DMODEL + c) = p1;
            }
        }
    }
}

// ---------------------------------------------------------------------------
// Flash attention with cp.async 2-stage K/V pipeline.
// Block: 256 threads = 8 warps; 128 queries/block. Key tile 64.
// ---------------------------------------------------------------------------
#define FKT 64
#define KVP 72
#define NFT (SEQ / FKT)   // 32

__global__ __launch_bounds__(256) void flash_f16(
    const __half* __restrict__ Qh, const __half* __restrict__ Kh,
    const __half* __restrict__ Vh, const uint32_t* __restrict__ mbits,
    __half* __restrict__ Ctx)
{
    __shared__ __align__(16) __half Ks[2][FKT * KVP];   // 2 x 9 KB
    __shared__ __align__(16) __half Vs[2][FKT * KVP];   // 2 x 9 KB

    const int tid  = threadIdx.x;
    const int w    = tid >> 5;
    const int lane = tid & 31;
    const int gid  = lane >> 2;
    const int ctid = lane & 3;

    const int h  = blockIdx.y;
    const int b  = blockIdx.z;
    const int qb = blockIdx.x * 128 + w * 16;

    // Q fragments held in registers (Q pre-scaled by 1/8)
    uint32_t qa[4][4];
    {
        const __half* q0 = Qh + (size_t)(b * SEQ + qb + gid    ) * DMODEL + h * DK;
        const __half* q1 = Qh + (size_t)(b * SEQ + qb + gid + 8) * DMODEL + h * DK;
#pragma unroll
        for (int t = 0; t < 4; t++) {
            qa[t][0] = *(const uint32_t*)(q0 + 16 * t + 2 * ctid);
            qa[t][1] = *(const uint32_t*)(q1 + 16 * t + 2 * ctid);
            qa[t][2] = *(const uint32_t*)(q0 + 16 * t + 2 * ctid + 8);
            qa[t][3] = *(const uint32_t*)(q1 + 16 * t + 2 * ctid + 8);
        }
    }

    float m0 = -INFINITY, m1 = -INFINITY, l0 = 0.f, l1 = 0.f;
    float o[8][4];
#pragma unroll
    for (int nd = 0; nd < 8; nd++)
#pragma unroll
        for (int t = 0; t < 4; t++) o[nd][t] = 0.f;

    const uint32_t* mb0 = mbits + ((size_t)(b * SEQ) + qb + gid) * MW;
    const uint32_t* mb1 = mb0 + 8 * MW;

    // per-thread KV load coords (2 x uint4 each for K and V)
    int kr[2], kc[2];
#pragma unroll
    for (int i = 0; i < 2; i++) {
        int f = i * 256 + tid;
        kr[i] = f >> 3;  kc[i] = (f & 7) * 8;
    }

    uint32_t ks_base[2], vs_base[2];
#pragma unroll
    for (int st = 0; st < 2; st++) {
        ks_base[st] = sptr(&Ks[st][(lane & 7) * KVP + (lane >> 3) * 8]);
        vs_base[st] = sptr(&Vs[st][((lane & 7) + (lane >> 3) * 8) * KVP]);
    }

    // prefetch tile 0
#pragma unroll
    for (int i = 0; i < 2; i++) {
        size_t ga = (size_t)(b * SEQ + kr[i]) * DMODEL + h * DK + kc[i];
        cp_async16(sptr(&Ks[0][kr[i] * KVP + kc[i]]), Kh + ga);
        cp_async16(sptr(&Vs[0][kr[i] * KVP + kc[i]]), Vh + ga);
    }
    CP_COMMIT();

    for (int ft = 0; ft < NFT; ft++) {
        const int cur = ft & 1;
        const int kt  = ft * FKT;
        if (ft + 1 < NFT) {
            const int nxt = (ft + 1) & 1;
#pragma unroll
            for (int i = 0; i < 2; i++) {
                size_t ga = (size_t)(b * SEQ + kt + FKT + kr[i]) * DMODEL + h * DK + kc[i];
                cp_async16(sptr(&Ks[nxt][kr[i] * KVP + kc[i]]), Kh + ga);
                cp_async16(sptr(&Vs[nxt][kr[i] * KVP + kc[i]]), Vh + ga);
            }
            CP_COMMIT();
            CP_WAIT(1);
        } else {
            CP_WAIT(0);
        }
        __syncthreads();

        uint2 w0 = *(const uint2*)(mb0 + (kt >> 5));
        uint2 w1 = *(const uint2*)(mb1 + (kt >> 5));

        // ---- S = Q K^T ----
        float sc[8][4];
#pragma unroll
        for (int nt = 0; nt < 8; nt++) {
#pragma unroll
            for (int t4 = 0; t4 < 4; t4++) sc[nt][t4] = 0.f;
            uint32_t bk[8];
            uint32_t base = ks_base[cur] + nt * 8 * KVP * 2;
            ldsm_x4(bk,     base);
            ldsm_x4(bk + 4, base + 64);
            mma_f16(sc[nt], qa[0], bk);
            mma_f16(sc[nt], qa[1], bk + 2);
            mma_f16(sc[nt], qa[2], bk + 4);
            mma_f16(sc[nt], qa[3], bk + 6);
        }

        // ---- mask from bits ----
#pragma unroll
        for (int nt = 0; nt < 8; nt++) {
            int kl = nt * 8 + 2 * ctid;
            uint32_t wr0 = (kl & 32) ? w0.y : w0.x;
            uint32_t wr1 = (kl & 32) ? w1.y : w1.x;
            int sh = kl & 31;
            if ((wr0 >> sh) & 1)       sc[nt][0] = NEGV;
            if ((wr0 >> (sh + 1)) & 1) sc[nt][1] = NEGV;
            if ((wr1 >> sh) & 1)       sc[nt][2] = NEGV;
            if ((wr1 >> (sh + 1)) & 1) sc[nt][3] = NEGV;
        }

        // ---- online softmax ----
        float t0 = sc[0][0], t1 = sc[0][2];
#pragma unroll
        for (int nt = 0; nt < 8; nt++) {
            t0 = fmaxf(t0, fmaxf(sc[nt][0], sc[nt][1]));
            t1 = fmaxf(t1, fmaxf(sc[nt][2], sc[nt][3]));
        }
        t0 = fmaxf(t0, __shfl_xor_sync(0xffffffffu, t0, 1));
        t0 = fmaxf(t0, __shfl_xor_sync(0xffffffffu, t0, 2));
        t1 = fmaxf(t1, __shfl_xor_sync(0xffffffffu, t1, 1));
        t1 = fmaxf(t1, __shfl_xor_sync(0xffffffffu, t1, 2));
        float nm0 = fmaxf(m0, t0), nm1 = fmaxf(m1, t1);
        float al0 = __expf(m0 - nm0), al1 = __expf(m1 - nm1);
        m0 = nm0; m1 = nm1;

        uint32_t pa[4][4];
        float ps0 = 0.f, ps1 = 0.f;
#pragma unroll
        for (int nt = 0; nt < 8; nt++) {
            float p00 = __expf(sc[nt][0] - nm0);
            float p01 = __expf(sc[nt][1] - nm0);
            float p10 = __expf(sc[nt][2] - nm1);
            float p11 = __expf(sc[nt][3] - nm1);
            ps0 += p00 + p01;
            ps1 += p10 + p11;
            int tt = nt >> 1;
            int hi = (nt & 1) ? 2 : 0;
            pa[tt][hi + 0] = pack_f16x2(p00, p01);
            pa[tt][hi + 1] = pack_f16x2(p10, p11);
        }
        ps0 += __shfl_xor_sync(0xffffffffu, ps0, 1);
        ps0 += __shfl_xor_sync(0xffffffffu, ps0, 2);
        ps1 += __shfl_xor_sync(0xffffffffu, ps1, 1);
        ps1 += __shfl_xor_sync(0xffffffffu, ps1, 2);
        l0 = l0 * al0 + ps0;
        l1 = l1 * al1 + ps1;

        // ---- O = O*alpha + P V ----
#pragma unroll
        for (int nd = 0; nd < 8; nd++) {
            o[nd][0] *= al0; o[nd][1] *= al0;
            o[nd][2] *= al1; o[nd][3] *= al1;
        }
#pragma unroll
        for (int nd = 0; nd < 8; nd++) {
            uint32_t bv[8];
            uint32_t base = vs_base[cur] + nd * 16;
            ldsm_x4_t(bv,     base);
            ldsm_x4_t(bv + 4, base + 32 * KVP * 2);
            mma_f16(o[nd], pa[0], bv);
            mma_f16(o[nd], pa[1], bv + 2);
            mma_f16(o[nd], pa[2], bv + 4);
            mma_f16(o[nd], pa[3], bv + 6);
        }
        __syncthreads();
    }

    // ---- normalize + store (fp16 ctx) ----
    float i0 = 1.f / l0, i1 = 1.f / l1;
    size_t r0 = (size_t)(b * SEQ + qb + gid);
#pragma unroll
    for (int nd = 0; nd < 8; nd++) {
        int c = h * DK + nd * 8 + 2 * ctid;
        uint32_t p0 = pack_f16x2(o[nd][0] * i0, o[nd][1] * i0);
        uint32_t p1 = pack_f16x2(o[nd][2] * i1, o[nd][3] * i1);
        *(uint32_t*)(Ctx + r0 * DMODEL + c)       = p0;
        *(uint32_t*)(Ctx + (r0 + 8) * DMODEL + c) = p1;
    }
}

// ---------------------------------------------------------------------------
// Launch
// ---------------------------------------------------------------------------
extern "C" void kernel_launch(void* const* d_in, const int* in_sizes, int n_in,
                              void* d_out, int out_size)
{
    const float* x    = (const float*)d_in[0];
    const int*   mask = (const int*)d_in[1];
    const float* Wq   = (const float*)d_in[2];
    const float* bq   = (const float*)d_in[3];
    const float* Wk   = (const float*)d_in[4];
    const float* bk   = (const float*)d_in[5];
    const float* Wv   = (const float*)d_in[6];
    const float* bv   = (const float*)d_in[7];
    const float* Wo   = (const float*)d_in[8];
    const float* bo   = (const float*)d_in[9];
    float* out = (float*)d_out;

    __half *Xh, *Wh, *Qh, *Kh, *Vh, *Ch; uint32_t* Mb;
    cudaGetSymbolAddress((void**)&Xh, g_Xh);
    cudaGetSymbolAddress((void**)&Wh, g_Wh);
    cudaGetSymbolAddress((void**)&Qh, g_Qh);
    cudaGetSymbolAddress((void**)&Kh, g_Kh);
    cudaGetSymbolAddress((void**)&Vh, g_Vh);
    cudaGetSymbolAddress((void**)&Ch, g_Ch);
    cudaGetSymbolAddress((void**)&Mb, g_Mb);

    pack_mask<<<BATCH * SEQ * MW / 8, 256>>>(mask, Mb);

    const int NX = MTOT * DMODEL / 4;
    const int NW = DMODEL * DMODEL / 4;
    cvt_f16<<<NX / 256, 256>>>(x,  Xh, NX);
    cvt_f16<<<NW / 256, 256>>>(Wq, Wh + 0 * DMODEL * DMODEL, NW);
    cvt_f16<<<NW / 256, 256>>>(Wk, Wh + 1 * DMODEL * DMODEL, NW);
    cvt_f16<<<NW / 256, 256>>>(Wv, Wh + 2 * DMODEL * DMODEL, NW);
    cvt_f16<<<NW / 256, 256>>>(Wo, Wh + 3 * DMODEL * DMODEL, NW);

    dim3 gg(DMODEL / TBN, MTOT / TBM);   // (8, 64)
    gemm_f16_t<__half><<<gg, 256>>>(Xh, Wh + 0 * DMODEL * DMODEL, bq, Qh, 0.125f);
    gemm_f16_t<__half><<<gg, 256>>>(Xh, Wh + 1 * DMODEL * DMODEL, bk, Kh, 1.0f);
    gemm_f16_t<__half><<<gg, 256>>>(Xh, Wh + 2 * DMODEL * DMODEL, bv, Vh, 1.0f);

    dim3 fg(SEQ / 128, NHEADS, BATCH);   // (16, 16, 4)
    flash_f16<<<fg, 256>>>(Qh, Kh, Vh, Mb, Ch);

    gemm_f16_t<float><<<gg, 256>>>(Ch, Wh + 3 * DMODEL * DMODEL, bo, out, 1.0f);
}